// round 8
// baseline (speedup 1.0000x reference)
#include <cuda_runtime.h>
#include <cuda_bf16.h>
#include <math.h>
#include <stdint.h>

#define N_NODES 50000
#define N_EDGES 640000
#define D 128
#define H 8

// ---------------- scratch (static device globals; no allocation) ----------------
__device__ float g_Q [N_NODES * D];
__device__ float g_Kf[N_NODES * D];
__device__ float g_Vf[N_NODES * D];
__device__ float g_x1[N_NODES * D];
__device__ float g_x2[N_NODES * D];
__device__ float g_stats[4 * D];
__device__ float g_bn1[2 * D];
__device__ float g_bn2[2 * D];
// bf16x2 (packed pairs) hi/lo buffers for GEMM A-operands
__device__ uint32_t g_hh [N_NODES * D / 2];   // h converted
__device__ uint32_t g_hl [N_NODES * D / 2];
__device__ uint32_t g_ah [N_NODES * D / 2];   // attn (gather output)
__device__ uint32_t g_al [N_NODES * D / 2];
__device__ uint32_t g_bx1h[N_NODES * D / 2];  // BN1(x1)
__device__ uint32_t g_bx1l[N_NODES * D / 2];
__device__ uint32_t g_mh [N_NODES * D];       // mid [N, 256]
__device__ uint32_t g_ml [N_NODES * D];
// CSR for dst-grouped edges
__device__ int g_rowptr[N_NODES + 1];
__device__ int g_cursor[N_NODES];
__device__ int g_csrc[N_EDGES];
__device__ int g_part[256];
// pre-converted weights
#define W_TOTAL 131072
__device__ __nv_bfloat16 g_wh[W_TOTAL];
__device__ __nv_bfloat16 g_wl[W_TOTAL];
#define OFF_WQ 0
#define OFF_WK 16384
#define OFF_WV 32768
#define OFF_WO 49152
#define OFF_W1 65536
#define OFF_W2 98304

// ---------------- helpers ----------------
__device__ __forceinline__ uint32_t smem_u32(const void* p) {
    uint32_t a;
    asm("{ .reg .u64 t; cvta.to.shared.u64 t, %1; cvt.u32.u64 %0, t; }" : "=r"(a) : "l"(p));
    return a;
}
__device__ __forceinline__ void ldm_x4(uint32_t& a0, uint32_t& a1, uint32_t& a2, uint32_t& a3,
                                       uint32_t addr) {
    asm volatile("ldmatrix.sync.aligned.m8n8.x4.shared.b16 {%0,%1,%2,%3}, [%4];"
                 : "=r"(a0), "=r"(a1), "=r"(a2), "=r"(a3) : "r"(addr));
}
__device__ __forceinline__ void ldm_x2(uint32_t& b0, uint32_t& b1, uint32_t addr) {
    asm volatile("ldmatrix.sync.aligned.m8n8.x2.shared.b16 {%0,%1}, [%2];"
                 : "=r"(b0), "=r"(b1) : "r"(addr));
}
__device__ __forceinline__ void mma_bf16(float* c, uint32_t a0, uint32_t a1, uint32_t a2,
                                         uint32_t a3, uint32_t b0, uint32_t b1) {
    asm volatile(
        "mma.sync.aligned.m16n8k16.row.col.f32.bf16.bf16.f32 "
        "{%0,%1,%2,%3}, {%4,%5,%6,%7}, {%8,%9}, {%0,%1,%2,%3};"
        : "+f"(c[0]), "+f"(c[1]), "+f"(c[2]), "+f"(c[3])
        : "r"(a0), "r"(a1), "r"(a2), "r"(a3), "r"(b0), "r"(b1));
}
__device__ __forceinline__ uint32_t split_pair(float a, float b, uint32_t& lo) {
    uint32_t h;
    asm("cvt.rn.bf16x2.f32 %0, %1, %2;" : "=r"(h) : "f"(b), "f"(a));
    float ra = a - __uint_as_float(h << 16);
    float rb = b - __uint_as_float(h & 0xffff0000u);
    asm("cvt.rn.bf16x2.f32 %0, %1, %2;" : "=r"(lo) : "f"(rb), "f"(ra));
    return h;
}
__device__ __forceinline__ void cp16(uint32_t dst, const void* src) {
    asm volatile("cp.async.cg.shared.global [%0], [%1], 16;" :: "r"(dst), "l"(src));
}
__device__ __forceinline__ void cp16z(uint32_t dst, const void* src, bool pred) {
    int sz = pred ? 16 : 0;
    asm volatile("cp.async.cg.shared.global [%0], [%1], 16, %2;"
                 :: "r"(dst), "l"(src), "r"(sz));
}
#define CP_COMMIT() asm volatile("cp.async.commit_group;" ::: "memory")
#define CP_WAIT0()  asm volatile("cp.async.wait_group 0;" ::: "memory")

// ---------------- weight conversion ----------------
__global__ void convert_weights(const float* __restrict__ WQ, const float* __restrict__ WK,
                                const float* __restrict__ WV, const float* __restrict__ WO,
                                const float* __restrict__ W1, const float* __restrict__ W2)
{
    int p = blockIdx.x * blockDim.x + threadIdx.x;
    if (p >= W_TOTAL / 2) return;
    int elem = p * 2;
    const float* src;
    int local;
    if (elem < OFF_W1) {
        int m = elem >> 14;
        local = elem & 16383;
        src = (m == 0) ? WQ : (m == 1) ? WK : (m == 2) ? WV : WO;
    } else if (elem < OFF_W2) {
        local = elem - OFF_W1;
        src = W1;
    } else {
        local = elem - OFF_W2;
        src = W2;
    }
    float a = src[local], b = src[local + 1];
    uint32_t lo;
    uint32_t hi = split_pair(a, b, lo);
    ((uint32_t*)g_wh)[p] = hi;
    ((uint32_t*)g_wl)[p] = lo;
}

// ---------------- h conversion ----------------
__global__ void convert_h(const float* __restrict__ h, int npair) {
    int p = blockIdx.x * blockDim.x + threadIdx.x;
    if (p >= npair) return;
    float2 v = ((const float2*)h)[p];
    uint32_t lo;
    uint32_t hi = split_pair(v.x, v.y, lo);
    g_hh[p] = hi;
    g_hl[p] = lo;
}

// ---------------- BN1(x1) conversion ----------------
__global__ void bn_convert(const float* __restrict__ x1, const float* __restrict__ bn,
                           int npair) {
    int p = blockIdx.x * blockDim.x + threadIdx.x;
    if (p >= npair) return;
    float2 v = ((const float2*)x1)[p];
    int col = (p * 2) & (D - 1);
    float a = v.x * bn[col] + bn[D + col];
    float b = v.y * bn[col + 1] + bn[D + col + 1];
    uint32_t lo;
    uint32_t hi = split_pair(a, b, lo);
    g_bx1h[p] = hi;
    g_bx1l[p] = lo;
}

// ---------------- zero ----------------
__global__ void zero_scratch() {
    int tid = blockIdx.x * blockDim.x + threadIdx.x;
    int stride = gridDim.x * blockDim.x;
    for (int i = tid; i < N_NODES; i += stride) g_cursor[i] = 0;
    if (tid < 4 * D) g_stats[tid] = 0.f;
}

// ---------------- CSR build ----------------
__global__ void hist_kernel(const int* __restrict__ dst, int E) {
    int e = blockIdx.x * blockDim.x + threadIdx.x;
    if (e < E) atomicAdd(&g_cursor[dst[e]], 1);
}

__global__ __launch_bounds__(256) void scan_local(int n) {
    int tid = threadIdx.x;
    int lane = tid & 31;
    int wid = tid >> 5;
    int i = blockIdx.x * 256 + tid;
    int c = (i < n) ? g_cursor[i] : 0;
    int v = c;
#pragma unroll
    for (int o = 1; o < 32; o <<= 1) {
        int t = __shfl_up_sync(0xffffffffu, v, o);
        if (lane >= o) v += t;
    }
    __shared__ int wsum[8];
    if (lane == 31) wsum[wid] = v;
    __syncthreads();
    if (wid == 0 && lane < 8) {
        int w = wsum[lane];
#pragma unroll
        for (int o = 1; o < 8; o <<= 1) {
            int t = __shfl_up_sync(0xffu, w, o);
            if (lane >= o) w += t;
        }
        wsum[lane] = w;
    }
    __syncthreads();
    int off = (wid > 0) ? wsum[wid - 1] : 0;
    if (i < n) g_rowptr[i] = v - c + off;
    if (tid == 255) g_part[blockIdx.x] = v + off;
}

__global__ __launch_bounds__(256) void scan_part(int nb) {
    int tid = threadIdx.x;
    int lane = tid & 31;
    int wid = tid >> 5;
    int p = (tid < nb) ? g_part[tid] : 0;
    int v = p;
#pragma unroll
    for (int o = 1; o < 32; o <<= 1) {
        int t = __shfl_up_sync(0xffffffffu, v, o);
        if (lane >= o) v += t;
    }
    __shared__ int wsum[8];
    if (lane == 31) wsum[wid] = v;
    __syncthreads();
    if (wid == 0 && lane < 8) {
        int w = wsum[lane];
#pragma unroll
        for (int o = 1; o < 8; o <<= 1) {
            int t = __shfl_up_sync(0xffu, w, o);
            if (lane >= o) w += t;
        }
        wsum[lane] = w;
    }
    __syncthreads();
    int off = (wid > 0) ? wsum[wid - 1] : 0;
    g_part[tid] = v - p + off;
}

__global__ __launch_bounds__(256) void scan_final(int n, int E) {
    int i = blockIdx.x * 256 + threadIdx.x;
    if (i < n) {
        int r = g_rowptr[i] + g_part[blockIdx.x];
        g_rowptr[i] = r;
        g_cursor[i] = r;
    }
    if (i == 0) g_rowptr[n] = E;
}

__global__ void scatter_kernel(const int* __restrict__ src, const int* __restrict__ dst, int E) {
    int e = blockIdx.x * blockDim.x + threadIdx.x;
    if (e < E) {
        int pos = atomicAdd(&g_cursor[dst[e]], 1);
        g_csrc[pos] = src[e];
    }
}

// ---------------- gather attention: warp per destination node, bf16 pair output --
__global__ __launch_bounds__(256) void gather_kernel(
    const float* __restrict__ Q, const float* __restrict__ K, const float* __restrict__ V,
    int n)
{
    int warp = (blockIdx.x * blockDim.x + threadIdx.x) >> 5;
    if (warp >= n) return;
    const int lid = threadIdx.x & 31;
    const int d = warp;

    float4 q = *(const float4*)(Q + (size_t)d * D + lid * 4);
    float4 acc = make_float4(0.f, 0.f, 0.f, 0.f);
    float zacc = 0.f;

    int beg = g_rowptr[d], end = g_rowptr[d + 1];
    int i = beg;
    for (; i + 2 <= end; i += 2) {
        int s0 = g_csrc[i], s1 = g_csrc[i + 1];
        float4 k0 = *(const float4*)(K + (size_t)s0 * D + lid * 4);
        float4 k1 = *(const float4*)(K + (size_t)s1 * D + lid * 4);
        float4 v0 = *(const float4*)(V + (size_t)s0 * D + lid * 4);
        float4 v1 = *(const float4*)(V + (size_t)s1 * D + lid * 4);
        float p0 = q.x * k0.x + q.y * k0.y + q.z * k0.z + q.w * k0.w;
        float p1 = q.x * k1.x + q.y * k1.y + q.z * k1.z + q.w * k1.w;
        p0 += __shfl_xor_sync(0xffffffffu, p0, 1);
        p1 += __shfl_xor_sync(0xffffffffu, p1, 1);
        p0 += __shfl_xor_sync(0xffffffffu, p0, 2);
        p1 += __shfl_xor_sync(0xffffffffu, p1, 2);
        float sc0 = __expf(fminf(fmaxf(p0 * 0.25f, -5.f), 5.f));
        float sc1 = __expf(fminf(fmaxf(p1 * 0.25f, -5.f), 5.f));
        acc.x += v0.x * sc0 + v1.x * sc1;
        acc.y += v0.y * sc0 + v1.y * sc1;
        acc.z += v0.z * sc0 + v1.z * sc1;
        acc.w += v0.w * sc0 + v1.w * sc1;
        zacc += sc0 + sc1;
    }
    if (i < end) {
        int s0 = g_csrc[i];
        float4 k0 = *(const float4*)(K + (size_t)s0 * D + lid * 4);
        float4 v0 = *(const float4*)(V + (size_t)s0 * D + lid * 4);
        float p0 = q.x * k0.x + q.y * k0.y + q.z * k0.z + q.w * k0.w;
        p0 += __shfl_xor_sync(0xffffffffu, p0, 1);
        p0 += __shfl_xor_sync(0xffffffffu, p0, 2);
        float sc0 = __expf(fminf(fmaxf(p0 * 0.25f, -5.f), 5.f));
        acc.x += v0.x * sc0; acc.y += v0.y * sc0;
        acc.z += v0.z * sc0; acc.w += v0.w * sc0;
        zacc += sc0;
    }
    float inv = 1.0f / zacc;
    acc.x *= inv; acc.y *= inv; acc.z *= inv; acc.w *= inv;
    uint32_t lo0, lo1;
    uint32_t hi0 = split_pair(acc.x, acc.y, lo0);
    uint32_t hi1 = split_pair(acc.z, acc.w, lo1);
    size_t idx = ((size_t)d * D + lid * 4) >> 1;
    *(uint2*)(g_ah + idx) = make_uint2(hi0, hi1);
    *(uint2*)(g_al + idx) = make_uint2(lo0, lo1);
}

// ---------------- tensor-core GEMM (all-bf16 operands) ----------------
enum { EPI_STORE = 0, EPI_BIAS_RESID = 1, EPI_BIAS_RELU = 2 };

#define SK 72
#define TILE_BYTES (128 * SK * 2)
#define DSMEM_BYTES (4 * TILE_BYTES)

template <int EPI, bool STATS, bool OUTPAIR, bool RESPAIR, int KT>
__device__ __forceinline__ void tgemm_core(
    const uint32_t* __restrict__ Ah, const uint32_t* __restrict__ Al,
    const __nv_bfloat16* __restrict__ Wh, const __nv_bfloat16* __restrict__ Wl,
    const float* __restrict__ bias, const float* __restrict__ resid,
    const uint32_t* __restrict__ resh, const uint32_t* __restrict__ resl,
    float* __restrict__ ssum, float* __restrict__ ssq,
    float* __restrict__ C, uint32_t* __restrict__ Ch, uint32_t* __restrict__ Cl,
    int M, int ldc, int rowBase, int colBase)
{
    extern __shared__ __align__(16) char sm[];
    char* sAhi = sm;
    char* sAlo = sm + TILE_BYTES;
    char* sWhi = sm + 2 * TILE_BYTES;
    char* sWlo = sm + 3 * TILE_BYTES;

    const int tid = threadIdx.x;
    const int wid = tid >> 5;
    const int lid = tid & 31;
    const int warp_m = wid & 1;
    const int warp_n = wid >> 1;

    const int ar = (lid & 7) + ((lid >> 3) & 1) * 8;
    const int ac = (lid >> 4) * 8;
    const int br = lid & 7;
    const int bc = ((lid >> 3) & 1) * 8;

    const uint32_t saHi = smem_u32(sAhi), saLo = smem_u32(sAlo);
    const uint32_t swHi = smem_u32(sWhi), swLo = smem_u32(sWlo);
    const uint32_t aOff = (uint32_t)((warp_m * 64 + ar) * SK + ac) * 2;
    const uint32_t bOff = (uint32_t)((warp_n * 32 + br) * SK + bc) * 2;

    float acc[4][4][4];
#pragma unroll
    for (int i = 0; i < 4; ++i)
#pragma unroll
        for (int j = 0; j < 4; ++j)
#pragma unroll
            for (int t = 0; t < 4; ++t) acc[i][j][t] = 0.f;

    const int row = tid >> 1;
    const int kh = (tid & 1) * 32;
    const int grow = rowBase + row;
    const bool valid = grow < M;

    constexpr int NSLAB = KT / 64;
#pragma unroll
    for (int slab = 0; slab < NSLAB; ++slab) {
        const int slabK = slab * 64;
        // A slab (bf16 pairs, zfill beyond M)
        {
            const uint32_t* Ar = Ah + (size_t)grow * (KT / 2) + (slabK + kh) / 2;
            const uint32_t* Al2 = Al + (size_t)grow * (KT / 2) + (slabK + kh) / 2;
            uint32_t dh = saHi + (uint32_t)(row * SK + kh) * 2;
            uint32_t dl = saLo + (uint32_t)(row * SK + kh) * 2;
#pragma unroll
            for (int c = 0; c < 4; ++c) cp16z(dh + c * 16, Ar + c * 4, valid);
#pragma unroll
            for (int c = 0; c < 4; ++c) cp16z(dl + c * 16, Al2 + c * 4, valid);
        }
        // W slab
        {
            const __nv_bfloat16* Whp = Wh + (size_t)(colBase + row) * KT + slabK + kh;
            const __nv_bfloat16* Wlp = Wl + (size_t)(colBase + row) * KT + slabK + kh;
            uint32_t dh = swHi + (uint32_t)(row * SK + kh) * 2;
            uint32_t dl = swLo + (uint32_t)(row * SK + kh) * 2;
#pragma unroll
            for (int c = 0; c < 4; ++c) cp16(dh + c * 16, Whp + c * 8);
#pragma unroll
            for (int c = 0; c < 4; ++c) cp16(dl + c * 16, Wlp + c * 8);
        }
        CP_COMMIT();
        CP_WAIT0();
        __syncthreads();

#pragma unroll
        for (int ks = 0; ks < 4; ++ks) {
            const uint32_t k0 = (uint32_t)(ks * 16) * 2;
            uint32_t bh[4][2], bl[4][2];
#pragma unroll
            for (int j = 0; j < 4; ++j) {
                uint32_t boff = bOff + (uint32_t)(j * 8 * SK) * 2 + k0;
                ldm_x2(bh[j][0], bh[j][1], swHi + boff);
                ldm_x2(bl[j][0], bl[j][1], swLo + boff);
            }
#pragma unroll
            for (int i = 0; i < 4; ++i) {
                uint32_t aoff = aOff + (uint32_t)(i * 16 * SK) * 2 + k0;
                uint32_t ah0, ah1, ah2, ah3, al0, al1, al2, al3;
                ldm_x4(ah0, ah1, ah2, ah3, saHi + aoff);
                ldm_x4(al0, al1, al2, al3, saLo + aoff);
#pragma unroll
                for (int j = 0; j < 4; ++j) {
                    mma_bf16(acc[i][j], ah0, ah1, ah2, ah3, bh[j][0], bh[j][1]);
                    mma_bf16(acc[i][j], ah0, ah1, ah2, ah3, bl[j][0], bl[j][1]);
                    mma_bf16(acc[i][j], al0, al1, al2, al3, bh[j][0], bh[j][1]);
                }
            }
        }
        if (slab + 1 < NSLAB) __syncthreads();
    }

    const int rr = lid >> 2;
    const int cc = (lid & 3) * 2;
    float cs[8], cq[8];
    if (STATS) {
#pragma unroll
        for (int t = 0; t < 8; ++t) { cs[t] = 0.f; cq[t] = 0.f; }
    }
#pragma unroll
    for (int i = 0; i < 4; ++i) {
#pragma unroll
        for (int half = 0; half < 2; ++half) {
            int r = rowBase + warp_m * 64 + i * 16 + rr + half * 8;
            if (r >= M) continue;
#pragma unroll
            for (int j = 0; j < 4; ++j) {
                int col = colBase + warp_n * 32 + j * 8 + cc;
                float v0 = acc[i][j][half * 2];
                float v1 = acc[i][j][half * 2 + 1];
                if (EPI == EPI_BIAS_RESID) {
                    v0 += bias[col];
                    v1 += bias[col + 1];
                    float r0, r1;
                    if (RESPAIR) {
                        size_t pidx = ((size_t)r * D + col) >> 1;
                        uint32_t rh = resh[pidx], rl = resl[pidx];
                        r0 = __uint_as_float(rh << 16) + __uint_as_float(rl << 16);
                        r1 = __uint_as_float(rh & 0xffff0000u) + __uint_as_float(rl & 0xffff0000u);
                    } else {
                        r0 = resid[(size_t)r * D + col];
                        r1 = resid[(size_t)r * D + col + 1];
                    }
                    v0 += r0; v1 += r1;
                } else if (EPI == EPI_BIAS_RELU) {
                    v0 = fmaxf(v0 + bias[col], 0.f);
                    v1 = fmaxf(v1 + bias[col + 1], 0.f);
                }
                if (STATS) {
                    cs[j * 2] += v0;     cq[j * 2] += v0 * v0;
                    cs[j * 2 + 1] += v1; cq[j * 2 + 1] += v1 * v1;
                }
                if (OUTPAIR) {
                    uint32_t lo;
                    uint32_t hi = split_pair(v0, v1, lo);
                    size_t pidx = ((size_t)r * ldc + col) >> 1;
                    Ch[pidx] = hi;
                    Cl[pidx] = lo;
                } else {
                    *(float2*)(C + (size_t)r * ldc + col) = make_float2(v0, v1);
                }
            }
        }
    }
    if (STATS) {
#pragma unroll
        for (int t = 0; t < 8; ++t) {
#pragma unroll
            for (int o = 4; o < 32; o <<= 1) {
                cs[t] += __shfl_xor_sync(0xffffffffu, cs[t], o);
                cq[t] += __shfl_xor_sync(0xffffffffu, cq[t], o);
            }
        }
        if (lid < 4) {
#pragma unroll
            for (int t = 0; t < 8; ++t) {
                int col = colBase + warp_n * 32 + (t >> 1) * 8 + lid * 2 + (t & 1);
                atomicAdd(&ssum[col & (D - 1)], cs[t]);
                atomicAdd(&ssq[col & (D - 1)], cq[t]);
            }
        }
    }
}

template <int EPI, bool STATS, bool OUTPAIR, bool RESPAIR, int KT>
__global__ __launch_bounds__(256, 2) void tgemm_k(
    const uint32_t* __restrict__ Ah, const uint32_t* __restrict__ Al,
    const __nv_bfloat16* __restrict__ Wh, const __nv_bfloat16* __restrict__ Wl,
    const float* __restrict__ bias, const float* __restrict__ resid,
    const uint32_t* __restrict__ resh, const uint32_t* __restrict__ resl,
    float* __restrict__ ssum, float* __restrict__ ssq,
    float* __restrict__ C, uint32_t* __restrict__ Ch, uint32_t* __restrict__ Cl,
    int M, int ldc)
{
    tgemm_core<EPI, STATS, OUTPAIR, RESPAIR, KT>(Ah, Al, Wh, Wl, bias, resid, resh, resl,
                                                 ssum, ssq, C, Ch, Cl, M, ldc,
                                                 blockIdx.x * 128, blockIdx.y * 128);
}

__global__ __launch_bounds__(256, 2) void qkv_kernel(
    float* __restrict__ Q, float* __restrict__ K, float* __restrict__ V, int M)
{
    int off = (blockIdx.y == 0) ? OFF_WQ : (blockIdx.y == 1) ? OFF_WK : OFF_WV;
    float* C = (blockIdx.y == 0) ? Q : (blockIdx.y == 1) ? K : V;
    tgemm_core<EPI_STORE, false, false, false, 128>(
        g_hh, g_hl, g_wh + off, g_wl + off, nullptr, nullptr, nullptr, nullptr,
        nullptr, nullptr, C, nullptr, nullptr, M, D, blockIdx.x * 128, 0);
}

// ---------------- batch-norm finalize/apply ----------------
__global__ void bn_finalize(const float* __restrict__ sum, const float* __restrict__ sq,
                            const float* __restrict__ g, const float* __restrict__ b,
                            float* __restrict__ scale, float* __restrict__ shift, int M)
{
    int c = threadIdx.x;
    float invM = 1.0f / (float)M;
    float mu = sum[c] * invM;
    float var = sq[c] * invM - mu * mu;
    float sc = g[c] * rsqrtf(var + 1e-5f);
    scale[c] = sc;
    shift[c] = b[c] - mu * sc;
}

__global__ void bn_apply(const float* __restrict__ x, const float* __restrict__ bn,
                         float* __restrict__ out, int M)
{
    int tid = blockIdx.x * blockDim.x + threadIdx.x;
    int stride = gridDim.x * blockDim.x;
    int total = M * D;
    for (int i = tid; i < total; i += stride) {
        int c = i & (D - 1);
        out[i] = x[i] * bn[c] + bn[D + c];
    }
}

// ---------------- host launch ----------------
extern "C" void kernel_launch(void* const* d_in, const int* in_sizes, int n_in,
                              void* d_out, int out_size)
{
    const float* h    = (const float*)d_in[0];
    const int*   src  = (const int*)d_in[1];
    const int*   dst  = (const int*)d_in[2];
    const float* WQ   = (const float*)d_in[3];
    const float* WK   = (const float*)d_in[4];
    const float* WV   = (const float*)d_in[5];
    const float* WO   = (const float*)d_in[6];
    const float* bO   = (const float*)d_in[7];
    const float* W1   = (const float*)d_in[8];
    const float* b1   = (const float*)d_in[9];
    const float* W2   = (const float*)d_in[10];
    const float* b2   = (const float*)d_in[11];
    const float* bn1g = (const float*)d_in[12];
    const float* bn1b = (const float*)d_in[13];
    const float* bn2g = (const float*)d_in[14];
    const float* bn2b = (const float*)d_in[15];
    float* out = (float*)d_out;

    int M = in_sizes[0] / D;
    int E = in_sizes[1];
    if (M > N_NODES) M = N_NODES;
    if (E > N_EDGES) E = N_EDGES;

    float *Qp, *Kp, *Vp, *x1p, *x2p, *stp, *bn1p, *bn2p;
    uint32_t *ahp, *alp, *bx1hp, *bx1lp, *mhp, *mlp;
    __nv_bfloat16 *whp, *wlp;
    cudaGetSymbolAddress((void**)&Qp,  g_Q);
    cudaGetSymbolAddress((void**)&Kp,  g_Kf);
    cudaGetSymbolAddress((void**)&Vp,  g_Vf);
    cudaGetSymbolAddress((void**)&x1p, g_x1);
    cudaGetSymbolAddress((void**)&x2p, g_x2);
    cudaGetSymbolAddress((void**)&stp, g_stats);
    cudaGetSymbolAddress((void**)&bn1p, g_bn1);
    cudaGetSymbolAddress((void**)&bn2p, g_bn2);
    cudaGetSymbolAddress((void**)&ahp, g_ah);
    cudaGetSymbolAddress((void**)&alp, g_al);
    cudaGetSymbolAddress((void**)&bx1hp, g_bx1h);
    cudaGetSymbolAddress((void**)&bx1lp, g_bx1l);
    cudaGetSymbolAddress((void**)&mhp, g_mh);
    cudaGetSymbolAddress((void**)&mlp, g_ml);
    cudaGetSymbolAddress((void**)&whp, g_wh);
    cudaGetSymbolAddress((void**)&wlp, g_wl);

    cudaFuncSetAttribute(qkv_kernel, cudaFuncAttributeMaxDynamicSharedMemorySize, DSMEM_BYTES);
    cudaFuncSetAttribute(tgemm_k<EPI_BIAS_RESID, true, false, false, 128>,
                         cudaFuncAttributeMaxDynamicSharedMemorySize, DSMEM_BYTES);
    cudaFuncSetAttribute(tgemm_k<EPI_BIAS_RELU, false, true, false, 128>,
                         cudaFuncAttributeMaxDynamicSharedMemorySize, DSMEM_BYTES);
    cudaFuncSetAttribute(tgemm_k<EPI_BIAS_RESID, true, false, true, 256>,
                         cudaFuncAttributeMaxDynamicSharedMemorySize, DSMEM_BYTES);

    dim3 blk(256);
    int gx = (M + 127) / 128;
    int nb = (M + 255) / 256;
    int npair = M * D / 2;
    int cvb = (npair + 255) / 256;

    zero_scratch<<<256, 256>>>();
    convert_weights<<<W_TOTAL / 2 / 256, 256>>>(WQ, WK, WV, WO, W1, W2);
    convert_h<<<cvb, 256>>>(h, npair);

    // CSR build
    hist_kernel<<<(E + 255) / 256, 256>>>(dst, E);
    scan_local<<<nb, 256>>>(M);
    scan_part<<<1, 256>>>(nb);
    scan_final<<<nb, 256>>>(M, E);
    scatter_kernel<<<(E + 255) / 256, 256>>>(src, dst, E);

    // QKV projections (bf16 A)
    qkv_kernel<<<dim3(gx, 3), blk, DSMEM_BYTES>>>(Qp, Kp, Vp, M);

    // gather attention -> bf16 pair attn
    gather_kernel<<<(M * 32 + 255) / 256, 256>>>(Qp, Kp, Vp, M);

    // O projection: attn @ WO^T + bO + h -> x1 (+ BN1 stats)
    tgemm_k<EPI_BIAS_RESID, true, false, false, 128><<<dim3(gx, 1), blk, DSMEM_BYTES>>>(
        ahp, alp, whp + OFF_WO, wlp + OFF_WO, bO, h, nullptr, nullptr,
        stp, stp + D, x1p, nullptr, nullptr, M, D);

    bn_finalize<<<1, D>>>(stp, stp + D, bn1g, bn1b, bn1p, bn1p + D, M);
    bn_convert<<<cvb, 256>>>(x1p, bn1p, npair);

    // FFN1: relu(BN1(x1) @ W1^T + b1) -> mid bf16 pair [N, 256]
    tgemm_k<EPI_BIAS_RELU, false, true, false, 128><<<dim3(gx, 2), blk, DSMEM_BYTES>>>(
        bx1hp, bx1lp, whp + OFF_W1, wlp + OFF_W1, b1, nullptr, nullptr, nullptr,
        nullptr, nullptr, nullptr, mhp, mlp, M, 2 * D);

    // FFN2: mid @ W2^T + b2 + BN1(x1) -> x2 (+ BN2 stats)
    tgemm_k<EPI_BIAS_RESID, true, false, true, 256><<<dim3(gx, 1), blk, DSMEM_BYTES>>>(
        mhp, mlp, whp + OFF_W2, wlp + OFF_W2, b2, nullptr, bx1hp, bx1lp,
        stp + 2 * D, stp + 3 * D, x2p, nullptr, nullptr, M, D);

    bn_finalize<<<1, D>>>(stp + 2 * D, stp + 3 * D, bn2g, bn2b, bn2p, bn2p + D, M);
    bn_apply<<<2048, 256>>>(x2p, bn2p, out, M);
}

// round 9
// speedup vs baseline: 1.0728x; 1.0728x over previous
#include <cuda_runtime.h>
#include <cuda_bf16.h>
#include <math.h>
#include <stdint.h>

#define N_NODES 50000
#define N_EDGES 640000
#define D 128
#define H 8

// ---------------- scratch (static device globals; no allocation) ----------------
__device__ float g_Q [N_NODES * D];
__device__ float g_Kf[N_NODES * D];
__device__ float g_Vf[N_NODES * D];
__device__ float g_x1[N_NODES * D];
__device__ float g_x2[N_NODES * D];
__device__ float g_stats[4 * D];
__device__ float g_bn1[2 * D];
__device__ float g_bn2[2 * D];
// bf16x2 (packed pairs) hi/lo buffers for GEMM A-operands
__device__ uint32_t g_hh [N_NODES * D / 2];
__device__ uint32_t g_hl [N_NODES * D / 2];
__device__ uint32_t g_ah [N_NODES * D / 2];
__device__ uint32_t g_al [N_NODES * D / 2];
__device__ uint32_t g_bx1h[N_NODES * D / 2];
__device__ uint32_t g_bx1l[N_NODES * D / 2];
__device__ uint32_t g_mh [N_NODES * D];
__device__ uint32_t g_ml [N_NODES * D];
// CSR
__device__ int g_rowptr[N_NODES + 1];
__device__ int g_cursor[N_NODES];
__device__ int g_csrc[N_EDGES];
__device__ int g_part[256];
// pre-converted weights
#define W_TOTAL 131072
__device__ __nv_bfloat16 g_wh[W_TOTAL];
__device__ __nv_bfloat16 g_wl[W_TOTAL];
#define OFF_WQ 0
#define OFF_WK 16384
#define OFF_WV 32768
#define OFF_WO 49152
#define OFF_W1 65536
#define OFF_W2 98304

// ---------------- helpers ----------------
__device__ __forceinline__ uint32_t smem_u32(const void* p) {
    uint32_t a;
    asm("{ .reg .u64 t; cvta.to.shared.u64 t, %1; cvt.u32.u64 %0, t; }" : "=r"(a) : "l"(p));
    return a;
}
__device__ __forceinline__ void ldm_x4(uint32_t& a0, uint32_t& a1, uint32_t& a2, uint32_t& a3,
                                       uint32_t addr) {
    asm volatile("ldmatrix.sync.aligned.m8n8.x4.shared.b16 {%0,%1,%2,%3}, [%4];"
                 : "=r"(a0), "=r"(a1), "=r"(a2), "=r"(a3) : "r"(addr));
}
__device__ __forceinline__ void ldm_x2(uint32_t& b0, uint32_t& b1, uint32_t addr) {
    asm volatile("ldmatrix.sync.aligned.m8n8.x2.shared.b16 {%0,%1}, [%2];"
                 : "=r"(b0), "=r"(b1) : "r"(addr));
}
__device__ __forceinline__ void mma_bf16(float* c, uint32_t a0, uint32_t a1, uint32_t a2,
                                         uint32_t a3, uint32_t b0, uint32_t b1) {
    asm volatile(
        "mma.sync.aligned.m16n8k16.row.col.f32.bf16.bf16.f32 "
        "{%0,%1,%2,%3}, {%4,%5,%6,%7}, {%8,%9}, {%0,%1,%2,%3};"
        : "+f"(c[0]), "+f"(c[1]), "+f"(c[2]), "+f"(c[3])
        : "r"(a0), "r"(a1), "r"(a2), "r"(a3), "r"(b0), "r"(b1));
}
__device__ __forceinline__ uint32_t split_pair(float a, float b, uint32_t& lo) {
    uint32_t h;
    asm("cvt.rn.bf16x2.f32 %0, %1, %2;" : "=r"(h) : "f"(b), "f"(a));
    float ra = a - __uint_as_float(h << 16);
    float rb = b - __uint_as_float(h & 0xffff0000u);
    asm("cvt.rn.bf16x2.f32 %0, %1, %2;" : "=r"(lo) : "f"(rb), "f"(ra));
    return h;
}
__device__ __forceinline__ void cp16(uint32_t dst, const void* src) {
    asm volatile("cp.async.cg.shared.global [%0], [%1], 16;" :: "r"(dst), "l"(src));
}
__device__ __forceinline__ void cp16z(uint32_t dst, const void* src, bool pred) {
    int sz = pred ? 16 : 0;
    asm volatile("cp.async.cg.shared.global [%0], [%1], 16, %2;"
                 :: "r"(dst), "l"(src), "r"(sz));
}
#define CP_COMMIT() asm volatile("cp.async.commit_group;" ::: "memory")
#define CP_WAIT0()  asm volatile("cp.async.wait_group 0;" ::: "memory")
#define CP_WAIT1()  asm volatile("cp.async.wait_group 1;" ::: "memory")

// ---------------- weight conversion ----------------
__global__ void convert_weights(const float* __restrict__ WQ, const float* __restrict__ WK,
                                const float* __restrict__ WV, const float* __restrict__ WO,
                                const float* __restrict__ W1, const float* __restrict__ W2)
{
    int p = blockIdx.x * blockDim.x + threadIdx.x;
    if (p >= W_TOTAL / 2) return;
    int elem = p * 2;
    const float* src;
    int local;
    if (elem < OFF_W1) {
        int m = elem >> 14;
        local = elem & 16383;
        src = (m == 0) ? WQ : (m == 1) ? WK : (m == 2) ? WV : WO;
    } else if (elem < OFF_W2) {
        local = elem - OFF_W1;
        src = W1;
    } else {
        local = elem - OFF_W2;
        src = W2;
    }
    float a = src[local], b = src[local + 1];
    uint32_t lo;
    uint32_t hi = split_pair(a, b, lo);
    ((uint32_t*)g_wh)[p] = hi;
    ((uint32_t*)g_wl)[p] = lo;
}

__global__ void convert_h(const float* __restrict__ h, int npair) {
    int p = blockIdx.x * blockDim.x + threadIdx.x;
    if (p >= npair) return;
    float2 v = ((const float2*)h)[p];
    uint32_t lo;
    uint32_t hi = split_pair(v.x, v.y, lo);
    g_hh[p] = hi;
    g_hl[p] = lo;
}

__global__ void bn_convert(const float* __restrict__ x1, const float* __restrict__ bn,
                           int npair) {
    int p = blockIdx.x * blockDim.x + threadIdx.x;
    if (p >= npair) return;
    float2 v = ((const float2*)x1)[p];
    int col = (p * 2) & (D - 1);
    float a = v.x * bn[col] + bn[D + col];
    float b = v.y * bn[col + 1] + bn[D + col + 1];
    uint32_t lo;
    uint32_t hi = split_pair(a, b, lo);
    g_bx1h[p] = hi;
    g_bx1l[p] = lo;
}

__global__ void zero_scratch() {
    int tid = blockIdx.x * blockDim.x + threadIdx.x;
    int stride = gridDim.x * blockDim.x;
    for (int i = tid; i < N_NODES; i += stride) g_cursor[i] = 0;
    if (tid < 4 * D) g_stats[tid] = 0.f;
}

// ---------------- CSR build ----------------
__global__ void hist_kernel(const int* __restrict__ dst, int E) {
    int e = blockIdx.x * blockDim.x + threadIdx.x;
    if (e < E) atomicAdd(&g_cursor[dst[e]], 1);
}

__global__ __launch_bounds__(256) void scan_local(int n) {
    int tid = threadIdx.x;
    int lane = tid & 31;
    int wid = tid >> 5;
    int i = blockIdx.x * 256 + tid;
    int c = (i < n) ? g_cursor[i] : 0;
    int v = c;
#pragma unroll
    for (int o = 1; o < 32; o <<= 1) {
        int t = __shfl_up_sync(0xffffffffu, v, o);
        if (lane >= o) v += t;
    }
    __shared__ int wsum[8];
    if (lane == 31) wsum[wid] = v;
    __syncthreads();
    if (wid == 0 && lane < 8) {
        int w = wsum[lane];
#pragma unroll
        for (int o = 1; o < 8; o <<= 1) {
            int t = __shfl_up_sync(0xffu, w, o);
            if (lane >= o) w += t;
        }
        wsum[lane] = w;
    }
    __syncthreads();
    int off = (wid > 0) ? wsum[wid - 1] : 0;
    if (i < n) g_rowptr[i] = v - c + off;
    if (tid == 255) g_part[blockIdx.x] = v + off;
}

__global__ __launch_bounds__(256) void scan_part(int nb) {
    int tid = threadIdx.x;
    int lane = tid & 31;
    int wid = tid >> 5;
    int p = (tid < nb) ? g_part[tid] : 0;
    int v = p;
#pragma unroll
    for (int o = 1; o < 32; o <<= 1) {
        int t = __shfl_up_sync(0xffffffffu, v, o);
        if (lane >= o) v += t;
    }
    __shared__ int wsum[8];
    if (lane == 31) wsum[wid] = v;
    __syncthreads();
    if (wid == 0 && lane < 8) {
        int w = wsum[lane];
#pragma unroll
        for (int o = 1; o < 8; o <<= 1) {
            int t = __shfl_up_sync(0xffu, w, o);
            if (lane >= o) w += t;
        }
        wsum[lane] = w;
    }
    __syncthreads();
    int off = (wid > 0) ? wsum[wid - 1] : 0;
    g_part[tid] = v - p + off;
}

__global__ __launch_bounds__(256) void scan_final(int n, int E) {
    int i = blockIdx.x * 256 + threadIdx.x;
    if (i < n) {
        int r = g_rowptr[i] + g_part[blockIdx.x];
        g_rowptr[i] = r;
        g_cursor[i] = r;
    }
    if (i == 0) g_rowptr[n] = E;
}

__global__ void scatter_kernel(const int* __restrict__ src, const int* __restrict__ dst, int E) {
    int e = blockIdx.x * blockDim.x + threadIdx.x;
    if (e < E) {
        int pos = atomicAdd(&g_cursor[dst[e]], 1);
        g_csrc[pos] = src[e];
    }
}

// ---------------- gather attention ----------------
__global__ __launch_bounds__(256) void gather_kernel(
    const float* __restrict__ Q, const float* __restrict__ K, const float* __restrict__ V,
    int n)
{
    int warp = (blockIdx.x * blockDim.x + threadIdx.x) >> 5;
    if (warp >= n) return;
    const int lid = threadIdx.x & 31;
    const int d = warp;

    float4 q = *(const float4*)(Q + (size_t)d * D + lid * 4);
    float4 acc = make_float4(0.f, 0.f, 0.f, 0.f);
    float zacc = 0.f;

    int beg = g_rowptr[d], end = g_rowptr[d + 1];
    int i = beg;
    for (; i + 2 <= end; i += 2) {
        int s0 = g_csrc[i], s1 = g_csrc[i + 1];
        float4 k0 = *(const float4*)(K + (size_t)s0 * D + lid * 4);
        float4 k1 = *(const float4*)(K + (size_t)s1 * D + lid * 4);
        float4 v0 = *(const float4*)(V + (size_t)s0 * D + lid * 4);
        float4 v1 = *(const float4*)(V + (size_t)s1 * D + lid * 4);
        float p0 = q.x * k0.x + q.y * k0.y + q.z * k0.z + q.w * k0.w;
        float p1 = q.x * k1.x + q.y * k1.y + q.z * k1.z + q.w * k1.w;
        p0 += __shfl_xor_sync(0xffffffffu, p0, 1);
        p1 += __shfl_xor_sync(0xffffffffu, p1, 1);
        p0 += __shfl_xor_sync(0xffffffffu, p0, 2);
        p1 += __shfl_xor_sync(0xffffffffu, p1, 2);
        float sc0 = __expf(fminf(fmaxf(p0 * 0.25f, -5.f), 5.f));
        float sc1 = __expf(fminf(fmaxf(p1 * 0.25f, -5.f), 5.f));
        acc.x += v0.x * sc0 + v1.x * sc1;
        acc.y += v0.y * sc0 + v1.y * sc1;
        acc.z += v0.z * sc0 + v1.z * sc1;
        acc.w += v0.w * sc0 + v1.w * sc1;
        zacc += sc0 + sc1;
    }
    if (i < end) {
        int s0 = g_csrc[i];
        float4 k0 = *(const float4*)(K + (size_t)s0 * D + lid * 4);
        float4 v0 = *(const float4*)(V + (size_t)s0 * D + lid * 4);
        float p0 = q.x * k0.x + q.y * k0.y + q.z * k0.z + q.w * k0.w;
        p0 += __shfl_xor_sync(0xffffffffu, p0, 1);
        p0 += __shfl_xor_sync(0xffffffffu, p0, 2);
        float sc0 = __expf(fminf(fmaxf(p0 * 0.25f, -5.f), 5.f));
        acc.x += v0.x * sc0; acc.y += v0.y * sc0;
        acc.z += v0.z * sc0; acc.w += v0.w * sc0;
        zacc += sc0;
    }
    float inv = 1.0f / zacc;
    acc.x *= inv; acc.y *= inv; acc.z *= inv; acc.w *= inv;
    uint32_t lo0, lo1;
    uint32_t hi0 = split_pair(acc.x, acc.y, lo0);
    uint32_t hi1 = split_pair(acc.z, acc.w, lo1);
    size_t idx = ((size_t)d * D + lid * 4) >> 1;
    *(uint2*)(g_ah + idx) = make_uint2(hi0, hi1);
    *(uint2*)(g_al + idx) = make_uint2(lo0, lo1);
}

// ---------------- tensor-core GEMM (2-stage cp.async pipeline) ----------------
enum { EPI_STORE = 0, EPI_BIAS_RESID = 1, EPI_BIAS_RELU = 2 };

#define BK 32
#define SKP 40                      // padded bf16 stride (32 + 8); 80B rows, conflict-free
#define TILEB (128 * SKP * 2)       // 10240 B per operand tile
#define STAGE_B (4 * TILEB)         // 40960 B per stage
#define DSMEM_BYTES (2 * STAGE_B)   // 81920 B

template <int EPI, bool STATS, bool OUTPAIR, bool RESPAIR, int KT>
__device__ __forceinline__ void tgemm_core(
    const uint32_t* __restrict__ Ah, const uint32_t* __restrict__ Al,
    const __nv_bfloat16* __restrict__ Wh, const __nv_bfloat16* __restrict__ Wl,
    const float* __restrict__ bias, const float* __restrict__ resid,
    const uint32_t* __restrict__ resh, const uint32_t* __restrict__ resl,
    float* __restrict__ ssum, float* __restrict__ ssq,
    float* __restrict__ C, uint32_t* __restrict__ Ch, uint32_t* __restrict__ Cl,
    int M, int ldc, int rowBase, int colBase)
{
    extern __shared__ __align__(16) char sm[];
    const uint32_t smbase = smem_u32(sm);

    const int tid = threadIdx.x;
    const int wid = tid >> 5;
    const int lid = tid & 31;
    const int warp_m = wid & 1;
    const int warp_n = wid >> 1;

    const int ar = (lid & 7) + ((lid >> 3) & 1) * 8;
    const int ac = (lid >> 4) * 8;
    const int br = lid & 7;
    const int bc = ((lid >> 3) & 1) * 8;

    const uint32_t aOff = (uint32_t)((warp_m * 64 + ar) * SKP + ac) * 2;
    const uint32_t bOff = (uint32_t)((warp_n * 32 + br) * SKP + bc) * 2;

    float acc[4][4][4];
#pragma unroll
    for (int i = 0; i < 4; ++i)
#pragma unroll
        for (int j = 0; j < 4; ++j)
#pragma unroll
            for (int t = 0; t < 4; ++t) acc[i][j][t] = 0.f;

    const int row = tid >> 1;
    const int half = tid & 1;
    const int grow = rowBase + row;
    const bool valid = grow < M;

    // per-thread global pointers (row fixed, advance by slab)
    const uint32_t* pAh = Ah + (size_t)grow * (KT / 2) + half * 8;
    const uint32_t* pAl = Al + (size_t)grow * (KT / 2) + half * 8;
    const __nv_bfloat16* pWh = Wh + (size_t)(colBase + row) * KT + half * 16;
    const __nv_bfloat16* pWl = Wl + (size_t)(colBase + row) * KT + half * 16;
    const uint32_t sdst = (uint32_t)(row * SKP + half * 16) * 2;

    auto load_slab = [&](int slab, int stage) {
        uint32_t sb = smbase + stage * STAGE_B + sdst;
        const uint32_t* a0 = pAh + slab * (BK / 2);
        const uint32_t* a1 = pAl + slab * (BK / 2);
        cp16z(sb, a0, valid);
        cp16z(sb + 16, a0 + 4, valid);
        cp16z(sb + TILEB, a1, valid);
        cp16z(sb + TILEB + 16, a1 + 4, valid);
        const __nv_bfloat16* w0 = pWh + slab * BK;
        const __nv_bfloat16* w1 = pWl + slab * BK;
        cp16(sb + 2 * TILEB, w0);
        cp16(sb + 2 * TILEB + 16, w0 + 8);
        cp16(sb + 3 * TILEB, w1);
        cp16(sb + 3 * TILEB + 16, w1 + 8);
        CP_COMMIT();
    };

    constexpr int NSLAB = KT / BK;
    load_slab(0, 0);
#pragma unroll
    for (int s = 0; s < NSLAB; ++s) {
        if (s + 1 < NSLAB) {
            load_slab(s + 1, (s + 1) & 1);
            CP_WAIT1();
        } else {
            CP_WAIT0();
        }
        __syncthreads();

        const uint32_t stA = smbase + (s & 1) * STAGE_B;
        const uint32_t stAl = stA + TILEB;
        const uint32_t stW = stA + 2 * TILEB;
        const uint32_t stWl = stA + 3 * TILEB;
#pragma unroll
        for (int ks = 0; ks < 2; ++ks) {
            const uint32_t k0 = (uint32_t)(ks * 16) * 2;
            uint32_t bh[4][2], bl[4][2];
#pragma unroll
            for (int j = 0; j < 4; ++j) {
                uint32_t boff = bOff + (uint32_t)(j * 8 * SKP) * 2 + k0;
                ldm_x2(bh[j][0], bh[j][1], stW + boff);
                ldm_x2(bl[j][0], bl[j][1], stWl + boff);
            }
#pragma unroll
            for (int i = 0; i < 4; ++i) {
                uint32_t aoff = aOff + (uint32_t)(i * 16 * SKP) * 2 + k0;
                uint32_t ah0, ah1, ah2, ah3, al0, al1, al2, al3;
                ldm_x4(ah0, ah1, ah2, ah3, stA + aoff);
                ldm_x4(al0, al1, al2, al3, stAl + aoff);
#pragma unroll
                for (int j = 0; j < 4; ++j) {
                    mma_bf16(acc[i][j], ah0, ah1, ah2, ah3, bh[j][0], bh[j][1]);
                    mma_bf16(acc[i][j], ah0, ah1, ah2, ah3, bl[j][0], bl[j][1]);
                    mma_bf16(acc[i][j], al0, al1, al2, al3, bh[j][0], bh[j][1]);
                }
            }
        }
        if (s + 2 < NSLAB + 1) __syncthreads();   // protect buffer reused by next prefetch
    }

    // ---- epilogue ----
    const int rr = lid >> 2;
    const int cc = (lid & 3) * 2;
    float cs[8], cq[8];
    if (STATS) {
#pragma unroll
        for (int t = 0; t < 8; ++t) { cs[t] = 0.f; cq[t] = 0.f; }
    }
#pragma unroll
    for (int i = 0; i < 4; ++i) {
#pragma unroll
        for (int half2 = 0; half2 < 2; ++half2) {
            int r = rowBase + warp_m * 64 + i * 16 + rr + half2 * 8;
            if (r >= M) continue;
#pragma unroll
            for (int j = 0; j < 4; ++j) {
                int col = colBase + warp_n * 32 + j * 8 + cc;
                float v0 = acc[i][j][half2 * 2];
                float v1 = acc[i][j][half2 * 2 + 1];
                if (EPI == EPI_BIAS_RESID) {
                    v0 += bias[col];
                    v1 += bias[col + 1];
                    float r0, r1;
                    if (RESPAIR) {
                        size_t pidx = ((size_t)r * D + col) >> 1;
                        uint32_t rh = resh[pidx], rl = resl[pidx];
                        r0 = __uint_as_float(rh << 16) + __uint_as_float(rl << 16);
                        r1 = __uint_as_float(rh & 0xffff0000u) + __uint_as_float(rl & 0xffff0000u);
                    } else {
                        r0 = resid[(size_t)r * D + col];
                        r1 = resid[(size_t)r * D + col + 1];
                    }
                    v0 += r0; v1 += r1;
                } else if (EPI == EPI_BIAS_RELU) {
                    v0 = fmaxf(v0 + bias[col], 0.f);
                    v1 = fmaxf(v1 + bias[col + 1], 0.f);
                }
                if (STATS) {
                    cs[j * 2] += v0;     cq[j * 2] += v0 * v0;
                    cs[j * 2 + 1] += v1; cq[j * 2 + 1] += v1 * v1;
                }
                if (OUTPAIR) {
                    uint32_t lo;
                    uint32_t hi = split_pair(v0, v1, lo);
                    size_t pidx = ((size_t)r * ldc + col) >> 1;
                    Ch[pidx] = hi;
                    Cl[pidx] = lo;
                } else {
                    *(float2*)(C + (size_t)r * ldc + col) = make_float2(v0, v1);
                }
            }
        }
    }
    if (STATS) {
#pragma unroll
        for (int t = 0; t < 8; ++t) {
#pragma unroll
            for (int o = 4; o < 32; o <<= 1) {
                cs[t] += __shfl_xor_sync(0xffffffffu, cs[t], o);
                cq[t] += __shfl_xor_sync(0xffffffffu, cq[t], o);
            }
        }
        if (lid < 4) {
#pragma unroll
            for (int t = 0; t < 8; ++t) {
                int col = colBase + warp_n * 32 + (t >> 1) * 8 + lid * 2 + (t & 1);
                atomicAdd(&ssum[col & (D - 1)], cs[t]);
                atomicAdd(&ssq[col & (D - 1)], cq[t]);
            }
        }
    }
}

template <int EPI, bool STATS, bool OUTPAIR, bool RESPAIR, int KT>
__global__ __launch_bounds__(256, 2) void tgemm_k(
    const uint32_t* __restrict__ Ah, const uint32_t* __restrict__ Al,
    const __nv_bfloat16* __restrict__ Wh, const __nv_bfloat16* __restrict__ Wl,
    const float* __restrict__ bias, const float* __restrict__ resid,
    const uint32_t* __restrict__ resh, const uint32_t* __restrict__ resl,
    float* __restrict__ ssum, float* __restrict__ ssq,
    float* __restrict__ C, uint32_t* __restrict__ Ch, uint32_t* __restrict__ Cl,
    int M, int ldc)
{
    tgemm_core<EPI, STATS, OUTPAIR, RESPAIR, KT>(Ah, Al, Wh, Wl, bias, resid, resh, resl,
                                                 ssum, ssq, C, Ch, Cl, M, ldc,
                                                 blockIdx.x * 128, blockIdx.y * 128);
}

__global__ __launch_bounds__(256, 2) void qkv_kernel(
    float* __restrict__ Q, float* __restrict__ K, float* __restrict__ V, int M)
{
    int off = (blockIdx.y == 0) ? OFF_WQ : (blockIdx.y == 1) ? OFF_WK : OFF_WV;
    float* C = (blockIdx.y == 0) ? Q : (blockIdx.y == 1) ? K : V;
    tgemm_core<EPI_STORE, false, false, false, 128>(
        g_hh, g_hl, g_wh + off, g_wl + off, nullptr, nullptr, nullptr, nullptr,
        nullptr, nullptr, C, nullptr, nullptr, M, D, blockIdx.x * 128, 0);
}

// ---------------- batch-norm finalize/apply ----------------
__global__ void bn_finalize(const float* __restrict__ sum, const float* __restrict__ sq,
                            const float* __restrict__ g, const float* __restrict__ b,
                            float* __restrict__ scale, float* __restrict__ shift, int M)
{
    int c = threadIdx.x;
    float invM = 1.0f / (float)M;
    float mu = sum[c] * invM;
    float var = sq[c] * invM - mu * mu;
    float sc = g[c] * rsqrtf(var + 1e-5f);
    scale[c] = sc;
    shift[c] = b[c] - mu * sc;
}

__global__ void bn_apply(const float* __restrict__ x, const float* __restrict__ bn,
                         float* __restrict__ out, int M)
{
    int tid = blockIdx.x * blockDim.x + threadIdx.x;
    int stride = gridDim.x * blockDim.x;
    int total = M * D;
    for (int i = tid; i < total; i += stride) {
        int c = i & (D - 1);
        out[i] = x[i] * bn[c] + bn[D + c];
    }
}

// ---------------- host launch ----------------
extern "C" void kernel_launch(void* const* d_in, const int* in_sizes, int n_in,
                              void* d_out, int out_size)
{
    const float* h    = (const float*)d_in[0];
    const int*   src  = (const int*)d_in[1];
    const int*   dst  = (const int*)d_in[2];
    const float* WQ   = (const float*)d_in[3];
    const float* WK   = (const float*)d_in[4];
    const float* WV   = (const float*)d_in[5];
    const float* WO   = (const float*)d_in[6];
    const float* bO   = (const float*)d_in[7];
    const float* W1   = (const float*)d_in[8];
    const float* b1   = (const float*)d_in[9];
    const float* W2   = (const float*)d_in[10];
    const float* b2   = (const float*)d_in[11];
    const float* bn1g = (const float*)d_in[12];
    const float* bn1b = (const float*)d_in[13];
    const float* bn2g = (const float*)d_in[14];
    const float* bn2b = (const float*)d_in[15];
    float* out = (float*)d_out;

    int M = in_sizes[0] / D;
    int E = in_sizes[1];
    if (M > N_NODES) M = N_NODES;
    if (E > N_EDGES) E = N_EDGES;

    float *Qp, *Kp, *Vp, *x1p, *x2p, *stp, *bn1p, *bn2p;
    uint32_t *ahp, *alp, *bx1hp, *bx1lp, *mhp, *mlp;
    __nv_bfloat16 *whp, *wlp;
    cudaGetSymbolAddress((void**)&Qp,  g_Q);
    cudaGetSymbolAddress((void**)&Kp,  g_Kf);
    cudaGetSymbolAddress((void**)&Vp,  g_Vf);
    cudaGetSymbolAddress((void**)&x1p, g_x1);
    cudaGetSymbolAddress((void**)&x2p, g_x2);
    cudaGetSymbolAddress((void**)&stp, g_stats);
    cudaGetSymbolAddress((void**)&bn1p, g_bn1);
    cudaGetSymbolAddress((void**)&bn2p, g_bn2);
    cudaGetSymbolAddress((void**)&ahp, g_ah);
    cudaGetSymbolAddress((void**)&alp, g_al);
    cudaGetSymbolAddress((void**)&bx1hp, g_bx1h);
    cudaGetSymbolAddress((void**)&bx1lp, g_bx1l);
    cudaGetSymbolAddress((void**)&mhp, g_mh);
    cudaGetSymbolAddress((void**)&mlp, g_ml);
    cudaGetSymbolAddress((void**)&whp, g_wh);
    cudaGetSymbolAddress((void**)&wlp, g_wl);

    cudaFuncSetAttribute(qkv_kernel, cudaFuncAttributeMaxDynamicSharedMemorySize, DSMEM_BYTES);
    cudaFuncSetAttribute(tgemm_k<EPI_BIAS_RESID, true, false, false, 128>,
                         cudaFuncAttributeMaxDynamicSharedMemorySize, DSMEM_BYTES);
    cudaFuncSetAttribute(tgemm_k<EPI_BIAS_RELU, false, true, false, 128>,
                         cudaFuncAttributeMaxDynamicSharedMemorySize, DSMEM_BYTES);
    cudaFuncSetAttribute(tgemm_k<EPI_BIAS_RESID, true, false, true, 256>,
                         cudaFuncAttributeMaxDynamicSharedMemorySize, DSMEM_BYTES);

    dim3 blk(256);
    int gx = (M + 127) / 128;
    int nb = (M + 255) / 256;
    int npair = M * D / 2;
    int cvb = (npair + 255) / 256;

    zero_scratch<<<256, 256>>>();
    convert_weights<<<W_TOTAL / 2 / 256, 256>>>(WQ, WK, WV, WO, W1, W2);
    convert_h<<<cvb, 256>>>(h, npair);

    // CSR build
    hist_kernel<<<(E + 255) / 256, 256>>>(dst, E);
    scan_local<<<nb, 256>>>(M);
    scan_part<<<1, 256>>>(nb);
    scan_final<<<nb, 256>>>(M, E);
    scatter_kernel<<<(E + 255) / 256, 256>>>(src, dst, E);

    // QKV projections
    qkv_kernel<<<dim3(gx, 3), blk, DSMEM_BYTES>>>(Qp, Kp, Vp, M);

    // gather attention -> bf16 pair attn
    gather_kernel<<<(M * 32 + 255) / 256, 256>>>(Qp, Kp, Vp, M);

    // O projection: attn @ WO^T + bO + h -> x1 (+ BN1 stats)
    tgemm_k<EPI_BIAS_RESID, true, false, false, 128><<<dim3(gx, 1), blk, DSMEM_BYTES>>>(
        ahp, alp, whp + OFF_WO, wlp + OFF_WO, bO, h, nullptr, nullptr,
        stp, stp + D, x1p, nullptr, nullptr, M, D);

    bn_finalize<<<1, D>>>(stp, stp + D, bn1g, bn1b, bn1p, bn1p + D, M);
    bn_convert<<<cvb, 256>>>(x1p, bn1p, npair);

    // FFN1: relu(BN1(x1) @ W1^T + b1) -> mid bf16 pair [N, 256]
    tgemm_k<EPI_BIAS_RELU, false, true, false, 128><<<dim3(gx, 2), blk, DSMEM_BYTES>>>(
        bx1hp, bx1lp, whp + OFF_W1, wlp + OFF_W1, b1, nullptr, nullptr, nullptr,
        nullptr, nullptr, nullptr, mhp, mlp, M, 2 * D);

    // FFN2: mid @ W2^T + b2 + BN1(x1) -> x2 (+ BN2 stats)
    tgemm_k<EPI_BIAS_RESID, true, false, true, 256><<<dim3(gx, 1), blk, DSMEM_BYTES>>>(
        mhp, mlp, whp + OFF_W2, wlp + OFF_W2, b2, nullptr, bx1hp, bx1lp,
        stp + 2 * D, stp + 3 * D, x2p, nullptr, nullptr, M, D);

    bn_finalize<<<1, D>>>(stp + 2 * D, stp + 3 * D, bn2g, bn2b, bn2p, bn2p + D, M);
    bn_apply<<<2048, 256>>>(x2p, bn2p, out, M);
}

// round 10
// speedup vs baseline: 1.3848x; 1.2908x over previous
#include <cuda_runtime.h>
#include <cuda_fp16.h>
#include <math.h>
#include <stdint.h>

#define N_NODES 50000
#define N_EDGES 640000
#define D 128
#define H 8

// ---------------- scratch (static device globals; no allocation) ----------------
__device__ float g_x1[N_NODES * D];
__device__ float g_x2[N_NODES * D];
__device__ float g_stats[4 * D];
__device__ float g_bn1[2 * D];
__device__ float g_bn2[2 * D];
// fp16x2-packed buffers
__device__ uint32_t g_Qh [N_NODES * D / 2];
__device__ uint32_t g_Kh [N_NODES * D / 2];
__device__ uint32_t g_Vh [N_NODES * D / 2];
__device__ uint32_t g_attn[N_NODES * D / 2];
__device__ uint32_t g_hh [N_NODES * D / 2];
__device__ uint32_t g_bx1[N_NODES * D / 2];
__device__ uint32_t g_midh[N_NODES * D];       // [N, 256] halves = N*128 uint32
// CSR
__device__ int g_rowptr[N_NODES + 1];
__device__ int g_cursor[N_NODES];
__device__ int g_csrc[N_EDGES];
__device__ int g_part[256];
// pre-converted weights (fp16)
#define W_TOTAL 131072
__device__ __half g_w[W_TOTAL];
#define OFF_WQ 0
#define OFF_WK 16384
#define OFF_WV 32768
#define OFF_WO 49152
#define OFF_W1 65536
#define OFF_W2 98304

// ---------------- helpers ----------------
__device__ __forceinline__ uint32_t smem_u32(const void* p) {
    uint32_t a;
    asm("{ .reg .u64 t; cvta.to.shared.u64 t, %1; cvt.u32.u64 %0, t; }" : "=r"(a) : "l"(p));
    return a;
}
__device__ __forceinline__ void ldm_x4(uint32_t& a0, uint32_t& a1, uint32_t& a2, uint32_t& a3,
                                       uint32_t addr) {
    asm volatile("ldmatrix.sync.aligned.m8n8.x4.shared.b16 {%0,%1,%2,%3}, [%4];"
                 : "=r"(a0), "=r"(a1), "=r"(a2), "=r"(a3) : "r"(addr));
}
__device__ __forceinline__ void ldm_x2(uint32_t& b0, uint32_t& b1, uint32_t addr) {
    asm volatile("ldmatrix.sync.aligned.m8n8.x2.shared.b16 {%0,%1}, [%2];"
                 : "=r"(b0), "=r"(b1) : "r"(addr));
}
__device__ __forceinline__ void mma_f16(float* c, uint32_t a0, uint32_t a1, uint32_t a2,
                                        uint32_t a3, uint32_t b0, uint32_t b1) {
    asm volatile(
        "mma.sync.aligned.m16n8k16.row.col.f32.f16.f16.f32 "
        "{%0,%1,%2,%3}, {%4,%5,%6,%7}, {%8,%9}, {%0,%1,%2,%3};"
        : "+f"(c[0]), "+f"(c[1]), "+f"(c[2]), "+f"(c[3])
        : "r"(a0), "r"(a1), "r"(a2), "r"(a3), "r"(b0), "r"(b1));
}
__device__ __forceinline__ uint32_t pack_h2(float a, float b) {
    uint32_t r;
    asm("cvt.rn.f16x2.f32 %0, %1, %2;" : "=r"(r) : "f"(b), "f"(a));
    return r;
}
__device__ __forceinline__ void cp16(uint32_t dst, const void* src) {
    asm volatile("cp.async.cg.shared.global [%0], [%1], 16;" :: "r"(dst), "l"(src));
}
__device__ __forceinline__ void cp16z(uint32_t dst, const void* src, bool pred) {
    int sz = pred ? 16 : 0;
    asm volatile("cp.async.cg.shared.global [%0], [%1], 16, %2;"
                 :: "r"(dst), "l"(src), "r"(sz));
}
#define CP_COMMIT() asm volatile("cp.async.commit_group;" ::: "memory")
#define CP_WAIT0()  asm volatile("cp.async.wait_group 0;" ::: "memory")
#define CP_WAIT1()  asm volatile("cp.async.wait_group 1;" ::: "memory")

// ---------------- weight conversion ----------------
__global__ void convert_weights(const float* __restrict__ WQ, const float* __restrict__ WK,
                                const float* __restrict__ WV, const float* __restrict__ WO,
                                const float* __restrict__ W1, const float* __restrict__ W2)
{
    int p = blockIdx.x * blockDim.x + threadIdx.x;
    if (p >= W_TOTAL / 2) return;
    int elem = p * 2;
    const float* src;
    int local;
    if (elem < OFF_W1) {
        int m = elem >> 14;
        local = elem & 16383;
        src = (m == 0) ? WQ : (m == 1) ? WK : (m == 2) ? WV : WO;
    } else if (elem < OFF_W2) {
        local = elem - OFF_W1;
        src = W1;
    } else {
        local = elem - OFF_W2;
        src = W2;
    }
    ((uint32_t*)g_w)[p] = pack_h2(src[local], src[local + 1]);
}

__global__ void convert_h(const float* __restrict__ h, int npair) {
    int p = blockIdx.x * blockDim.x + threadIdx.x;
    if (p >= npair) return;
    float2 v = ((const float2*)h)[p];
    g_hh[p] = pack_h2(v.x, v.y);
}

__global__ void bn_convert(const float* __restrict__ x1, const float* __restrict__ bn,
                           int npair) {
    int p = blockIdx.x * blockDim.x + threadIdx.x;
    if (p >= npair) return;
    float2 v = ((const float2*)x1)[p];
    int col = (p * 2) & (D - 1);
    g_bx1[p] = pack_h2(v.x * bn[col] + bn[D + col], v.y * bn[col + 1] + bn[D + col + 1]);
}

__global__ void zero_scratch() {
    int tid = blockIdx.x * blockDim.x + threadIdx.x;
    int stride = gridDim.x * blockDim.x;
    for (int i = tid; i < N_NODES; i += stride) g_cursor[i] = 0;
    if (tid < 4 * D) g_stats[tid] = 0.f;
}

// ---------------- CSR build ----------------
__global__ void hist_kernel(const int* __restrict__ dst, int E) {
    int e = blockIdx.x * blockDim.x + threadIdx.x;
    if (e < E) atomicAdd(&g_cursor[dst[e]], 1);
}

__global__ __launch_bounds__(256) void scan_local(int n) {
    int tid = threadIdx.x;
    int lane = tid & 31;
    int wid = tid >> 5;
    int i = blockIdx.x * 256 + tid;
    int c = (i < n) ? g_cursor[i] : 0;
    int v = c;
#pragma unroll
    for (int o = 1; o < 32; o <<= 1) {
        int t = __shfl_up_sync(0xffffffffu, v, o);
        if (lane >= o) v += t;
    }
    __shared__ int wsum[8];
    if (lane == 31) wsum[wid] = v;
    __syncthreads();
    if (wid == 0 && lane < 8) {
        int w = wsum[lane];
#pragma unroll
        for (int o = 1; o < 8; o <<= 1) {
            int t = __shfl_up_sync(0xffu, w, o);
            if (lane >= o) w += t;
        }
        wsum[lane] = w;
    }
    __syncthreads();
    int off = (wid > 0) ? wsum[wid - 1] : 0;
    if (i < n) g_rowptr[i] = v - c + off;
    if (tid == 255) g_part[blockIdx.x] = v + off;
}

__global__ __launch_bounds__(256) void scan_part(int nb) {
    int tid = threadIdx.x;
    int lane = tid & 31;
    int wid = tid >> 5;
    int p = (tid < nb) ? g_part[tid] : 0;
    int v = p;
#pragma unroll
    for (int o = 1; o < 32; o <<= 1) {
        int t = __shfl_up_sync(0xffffffffu, v, o);
        if (lane >= o) v += t;
    }
    __shared__ int wsum[8];
    if (lane == 31) wsum[wid] = v;
    __syncthreads();
    if (wid == 0 && lane < 8) {
        int w = wsum[lane];
#pragma unroll
        for (int o = 1; o < 8; o <<= 1) {
            int t = __shfl_up_sync(0xffu, w, o);
            if (lane >= o) w += t;
        }
        wsum[lane] = w;
    }
    __syncthreads();
    int off = (wid > 0) ? wsum[wid - 1] : 0;
    g_part[tid] = v - p + off;
}

__global__ __launch_bounds__(256) void scan_final(int n, int E) {
    int i = blockIdx.x * 256 + threadIdx.x;
    if (i < n) {
        int r = g_rowptr[i] + g_part[blockIdx.x];
        g_rowptr[i] = r;
        g_cursor[i] = r;
    }
    if (i == 0) g_rowptr[n] = E;
}

__global__ void scatter_kernel(const int* __restrict__ src, const int* __restrict__ dst, int E) {
    int e = blockIdx.x * blockDim.x + threadIdx.x;
    if (e < E) {
        int pos = atomicAdd(&g_cursor[dst[e]], 1);
        g_csrc[pos] = src[e];
    }
}

// ---------------- gather attention: fp16 K/V, warp per node ----------------
__device__ __forceinline__ float4 unp4(uint2 u) {
    float2 a = __half22float2(*reinterpret_cast<const __half2*>(&u.x));
    float2 b = __half22float2(*reinterpret_cast<const __half2*>(&u.y));
    return make_float4(a.x, a.y, b.x, b.y);
}

__global__ __launch_bounds__(256) void gather_kernel(int n) {
    int warp = (blockIdx.x * blockDim.x + threadIdx.x) >> 5;
    if (warp >= n) return;
    const int lid = threadIdx.x & 31;
    const int d = warp;
    const size_t base = (size_t)d * (D / 2) + lid * 2;

    float4 q = unp4(*(const uint2*)(g_Qh + base));
    float4 acc = make_float4(0.f, 0.f, 0.f, 0.f);
    float zacc = 0.f;

    int beg = g_rowptr[d], end = g_rowptr[d + 1];
    int i = beg;
    for (; i + 2 <= end; i += 2) {
        int s0 = g_csrc[i], s1 = g_csrc[i + 1];
        size_t o0 = (size_t)s0 * (D / 2) + lid * 2;
        size_t o1 = (size_t)s1 * (D / 2) + lid * 2;
        float4 k0 = unp4(*(const uint2*)(g_Kh + o0));
        float4 k1 = unp4(*(const uint2*)(g_Kh + o1));
        float4 v0 = unp4(*(const uint2*)(g_Vh + o0));
        float4 v1 = unp4(*(const uint2*)(g_Vh + o1));
        float p0 = q.x * k0.x + q.y * k0.y + q.z * k0.z + q.w * k0.w;
        float p1 = q.x * k1.x + q.y * k1.y + q.z * k1.z + q.w * k1.w;
        p0 += __shfl_xor_sync(0xffffffffu, p0, 1);
        p1 += __shfl_xor_sync(0xffffffffu, p1, 1);
        p0 += __shfl_xor_sync(0xffffffffu, p0, 2);
        p1 += __shfl_xor_sync(0xffffffffu, p1, 2);
        float sc0 = __expf(fminf(fmaxf(p0 * 0.25f, -5.f), 5.f));
        float sc1 = __expf(fminf(fmaxf(p1 * 0.25f, -5.f), 5.f));
        acc.x += v0.x * sc0 + v1.x * sc1;
        acc.y += v0.y * sc0 + v1.y * sc1;
        acc.z += v0.z * sc0 + v1.z * sc1;
        acc.w += v0.w * sc0 + v1.w * sc1;
        zacc += sc0 + sc1;
    }
    if (i < end) {
        int s0 = g_csrc[i];
        size_t o0 = (size_t)s0 * (D / 2) + lid * 2;
        float4 k0 = unp4(*(const uint2*)(g_Kh + o0));
        float4 v0 = unp4(*(const uint2*)(g_Vh + o0));
        float p0 = q.x * k0.x + q.y * k0.y + q.z * k0.z + q.w * k0.w;
        p0 += __shfl_xor_sync(0xffffffffu, p0, 1);
        p0 += __shfl_xor_sync(0xffffffffu, p0, 2);
        float sc0 = __expf(fminf(fmaxf(p0 * 0.25f, -5.f), 5.f));
        acc.x += v0.x * sc0; acc.y += v0.y * sc0;
        acc.z += v0.z * sc0; acc.w += v0.w * sc0;
        zacc += sc0;
    }
    float inv = 1.0f / zacc;
    *(uint2*)(g_attn + base) = make_uint2(pack_h2(acc.x * inv, acc.y * inv),
                                          pack_h2(acc.z * inv, acc.w * inv));
}

// ---------------- tensor-core GEMM: single-pass fp16, 2-stage pipeline ----------
enum { EPI_STORE_H = 0, EPI_BIAS_RESID = 1, EPI_BIAS_RELU_H = 2 };

#define BK 64
#define SK 72                        // padded fp16 stride
#define TILEB (128 * SK * 2)         // 18432 B
#define STAGE_B (2 * TILEB)          // 36864 B
#define DSMEM_BYTES (2 * STAGE_B)    // 73728 B

template <int EPI, bool STATS, bool RESBN, int KT>
__device__ __forceinline__ void tgemm_core(
    const __half* __restrict__ A, const __half* __restrict__ W,
    const float* __restrict__ bias, const float* __restrict__ resid,
    const float* __restrict__ t0, const float* __restrict__ t1,
    float* __restrict__ ssum, float* __restrict__ ssq,
    float* __restrict__ Cf, uint32_t* __restrict__ Ch,
    int M, int ldc, int rowBase, int colBase)
{
    extern __shared__ __align__(16) char sm[];
    const uint32_t smbase = smem_u32(sm);

    const int tid = threadIdx.x;
    const int wid = tid >> 5;
    const int lid = tid & 31;
    const int warp_m = wid & 1;
    const int warp_n = wid >> 1;

    const int ar = (lid & 7) + ((lid >> 3) & 1) * 8;
    const int ac = (lid >> 4) * 8;
    const int br = lid & 7;
    const int bc = ((lid >> 3) & 1) * 8;

    const uint32_t aOff = (uint32_t)((warp_m * 64 + ar) * SK + ac) * 2;
    const uint32_t bOff = (uint32_t)((warp_n * 32 + br) * SK + bc) * 2;

    float acc[4][4][4];
#pragma unroll
    for (int i = 0; i < 4; ++i)
#pragma unroll
        for (int j = 0; j < 4; ++j)
#pragma unroll
            for (int t = 0; t < 4; ++t) acc[i][j][t] = 0.f;

    const int row = tid >> 1;
    const int kh = (tid & 1) * 32;   // fp16 elems within 64-slab
    const int grow = rowBase + row;
    const bool valid = grow < M;

    const __half* pA = A + (size_t)grow * KT + kh;
    const __half* pW = W + (size_t)(colBase + row) * KT + kh;
    const uint32_t sdst = (uint32_t)(row * SK + kh) * 2;

    auto load_slab = [&](int slab, int stage) {
        uint32_t sb = smbase + stage * STAGE_B + sdst;
        const __half* a = pA + slab * BK;
        const __half* w = pW + slab * BK;
#pragma unroll
        for (int c = 0; c < 4; ++c) cp16z(sb + c * 16, a + c * 8, valid);
#pragma unroll
        for (int c = 0; c < 4; ++c) cp16(sb + TILEB + c * 16, w + c * 8);
        CP_COMMIT();
    };

    constexpr int NSLAB = KT / BK;
    load_slab(0, 0);
#pragma unroll
    for (int s = 0; s < NSLAB; ++s) {
        if (s + 1 < NSLAB) {
            load_slab(s + 1, (s + 1) & 1);
            CP_WAIT1();
        } else {
            CP_WAIT0();
        }
        __syncthreads();

        const uint32_t stA = smbase + (s & 1) * STAGE_B;
        const uint32_t stW = stA + TILEB;
#pragma unroll
        for (int ks = 0; ks < 4; ++ks) {
            const uint32_t k0 = (uint32_t)(ks * 16) * 2;
            uint32_t bh[4][2];
#pragma unroll
            for (int j = 0; j < 4; ++j)
                ldm_x2(bh[j][0], bh[j][1], stW + bOff + (uint32_t)(j * 8 * SK) * 2 + k0);
#pragma unroll
            for (int i = 0; i < 4; ++i) {
                uint32_t a0, a1, a2, a3;
                ldm_x4(a0, a1, a2, a3, stA + aOff + (uint32_t)(i * 16 * SK) * 2 + k0);
#pragma unroll
                for (int j = 0; j < 4; ++j)
                    mma_f16(acc[i][j], a0, a1, a2, a3, bh[j][0], bh[j][1]);
            }
        }
        if (s + 1 < NSLAB) __syncthreads();
    }

    // ---- epilogue ----
    const int rr = lid >> 2;
    const int cc = (lid & 3) * 2;
    float cs[8], cq[8];
    if (STATS) {
#pragma unroll
        for (int t = 0; t < 8; ++t) { cs[t] = 0.f; cq[t] = 0.f; }
    }
#pragma unroll
    for (int i = 0; i < 4; ++i) {
#pragma unroll
        for (int hf = 0; hf < 2; ++hf) {
            int r = rowBase + warp_m * 64 + i * 16 + rr + hf * 8;
            if (r >= M) continue;
#pragma unroll
            for (int j = 0; j < 4; ++j) {
                int col = colBase + warp_n * 32 + j * 8 + cc;
                float v0 = acc[i][j][hf * 2];
                float v1 = acc[i][j][hf * 2 + 1];
                if (EPI == EPI_BIAS_RESID) {
                    v0 += bias[col];
                    v1 += bias[col + 1];
                    float r0 = resid[(size_t)r * D + col];
                    float r1 = resid[(size_t)r * D + col + 1];
                    if (RESBN) {
                        r0 = r0 * t0[col] + t1[col];
                        r1 = r1 * t0[col + 1] + t1[col + 1];
                    }
                    v0 += r0; v1 += r1;
                } else if (EPI == EPI_BIAS_RELU_H) {
                    v0 = fmaxf(v0 + bias[col], 0.f);
                    v1 = fmaxf(v1 + bias[col + 1], 0.f);
                }
                if (STATS) {
                    cs[j * 2] += v0;     cq[j * 2] += v0 * v0;
                    cs[j * 2 + 1] += v1; cq[j * 2 + 1] += v1 * v1;
                }
                if (EPI == EPI_BIAS_RESID) {
                    *(float2*)(Cf + (size_t)r * ldc + col) = make_float2(v0, v1);
                } else {
                    Ch[((size_t)r * ldc + col) >> 1] = pack_h2(v0, v1);
                }
            }
        }
    }
    if (STATS) {
#pragma unroll
        for (int t = 0; t < 8; ++t) {
#pragma unroll
            for (int o = 4; o < 32; o <<= 1) {
                cs[t] += __shfl_xor_sync(0xffffffffu, cs[t], o);
                cq[t] += __shfl_xor_sync(0xffffffffu, cq[t], o);
            }
        }
        if (lid < 4) {
#pragma unroll
            for (int t = 0; t < 8; ++t) {
                int col = colBase + warp_n * 32 + (t >> 1) * 8 + lid * 2 + (t & 1);
                atomicAdd(&ssum[col & (D - 1)], cs[t]);
                atomicAdd(&ssq[col & (D - 1)], cq[t]);
            }
        }
    }
}

template <int EPI, bool STATS, bool RESBN, int KT>
__global__ __launch_bounds__(256, 2) void tgemm_k(
    const __half* __restrict__ A, const __half* __restrict__ W,
    const float* __restrict__ bias, const float* __restrict__ resid,
    const float* __restrict__ t0, const float* __restrict__ t1,
    float* __restrict__ ssum, float* __restrict__ ssq,
    float* __restrict__ Cf, uint32_t* __restrict__ Ch, int M, int ldc)
{
    tgemm_core<EPI, STATS, RESBN, KT>(A, W, bias, resid, t0, t1, ssum, ssq, Cf, Ch,
                                      M, ldc, blockIdx.x * 128, blockIdx.y * 128);
}

__global__ __launch_bounds__(256, 2) void qkv_kernel(int M) {
    int off = (blockIdx.y == 0) ? OFF_WQ : (blockIdx.y == 1) ? OFF_WK : OFF_WV;
    uint32_t* C = (blockIdx.y == 0) ? g_Qh : (blockIdx.y == 1) ? g_Kh : g_Vh;
    tgemm_core<EPI_STORE_H, false, false, 128>(
        (const __half*)g_hh, g_w + off, nullptr, nullptr, nullptr, nullptr,
        nullptr, nullptr, nullptr, C, M, D, blockIdx.x * 128, 0);
}

// ---------------- batch-norm finalize/apply ----------------
__global__ void bn_finalize(const float* __restrict__ sum, const float* __restrict__ sq,
                            const float* __restrict__ g, const float* __restrict__ b,
                            float* __restrict__ scale, float* __restrict__ shift, int M)
{
    int c = threadIdx.x;
    float invM = 1.0f / (float)M;
    float mu = sum[c] * invM;
    float var = sq[c] * invM - mu * mu;
    float sc = g[c] * rsqrtf(var + 1e-5f);
    scale[c] = sc;
    shift[c] = b[c] - mu * sc;
}

__global__ void bn_apply(const float* __restrict__ x, const float* __restrict__ bn,
                         float* __restrict__ out, int M)
{
    int tid = blockIdx.x * blockDim.x + threadIdx.x;
    int stride = gridDim.x * blockDim.x;
    int total = M * D;
    for (int i = tid; i < total; i += stride) {
        int c = i & (D - 1);
        out[i] = x[i] * bn[c] + bn[D + c];
    }
}

// ---------------- host launch ----------------
extern "C" void kernel_launch(void* const* d_in, const int* in_sizes, int n_in,
                              void* d_out, int out_size)
{
    const float* h    = (const float*)d_in[0];
    const int*   src  = (const int*)d_in[1];
    const int*   dst  = (const int*)d_in[2];
    const float* WQ   = (const float*)d_in[3];
    const float* WK   = (const float*)d_in[4];
    const float* WV   = (const float*)d_in[5];
    const float* WO   = (const float*)d_in[6];
    const float* bO   = (const float*)d_in[7];
    const float* W1   = (const float*)d_in[8];
    const float* b1   = (const float*)d_in[9];
    const float* W2   = (const float*)d_in[10];
    const float* b2   = (const float*)d_in[11];
    const float* bn1g = (const float*)d_in[12];
    const float* bn1b = (const float*)d_in[13];
    const float* bn2g = (const float*)d_in[14];
    const float* bn2b = (const float*)d_in[15];
    float* out = (float*)d_out;

    int M = in_sizes[0] / D;
    int E = in_sizes[1];
    if (M > N_NODES) M = N_NODES;
    if (E > N_EDGES) E = N_EDGES;

    float *x1p, *x2p, *stp, *bn1p, *bn2p;
    uint32_t *attnp, *bx1p, *midp;
    __half *wp;
    cudaGetSymbolAddress((void**)&x1p, g_x1);
    cudaGetSymbolAddress((void**)&x2p, g_x2);
    cudaGetSymbolAddress((void**)&stp, g_stats);
    cudaGetSymbolAddress((void**)&bn1p, g_bn1);
    cudaGetSymbolAddress((void**)&bn2p, g_bn2);
    cudaGetSymbolAddress((void**)&attnp, g_attn);
    cudaGetSymbolAddress((void**)&bx1p, g_bx1);
    cudaGetSymbolAddress((void**)&midp, g_midh);
    cudaGetSymbolAddress((void**)&wp, g_w);

    cudaFuncSetAttribute(qkv_kernel, cudaFuncAttributeMaxDynamicSharedMemorySize, DSMEM_BYTES);
    cudaFuncSetAttribute(tgemm_k<EPI_BIAS_RESID, true, false, 128>,
                         cudaFuncAttributeMaxDynamicSharedMemorySize, DSMEM_BYTES);
    cudaFuncSetAttribute(tgemm_k<EPI_BIAS_RELU_H, false, false, 128>,
                         cudaFuncAttributeMaxDynamicSharedMemorySize, DSMEM_BYTES);
    cudaFuncSetAttribute(tgemm_k<EPI_BIAS_RESID, true, true, 256>,
                         cudaFuncAttributeMaxDynamicSharedMemorySize, DSMEM_BYTES);

    dim3 blk(256);
    int gx = (M + 127) / 128;
    int nb = (M + 255) / 256;
    int npair = M * D / 2;
    int cvb = (npair + 255) / 256;

    zero_scratch<<<256, 256>>>();
    convert_weights<<<W_TOTAL / 2 / 256, 256>>>(WQ, WK, WV, WO, W1, W2);
    convert_h<<<cvb, 256>>>(h, npair);

    // CSR build
    hist_kernel<<<(E + 255) / 256, 256>>>(dst, E);
    scan_local<<<nb, 256>>>(M);
    scan_part<<<1, 256>>>(nb);
    scan_final<<<nb, 256>>>(M, E);
    scatter_kernel<<<(E + 255) / 256, 256>>>(src, dst, E);

    // QKV projections (fp16 single-pass)
    qkv_kernel<<<dim3(gx, 3), blk, DSMEM_BYTES>>>(M);

    // gather attention (fp16 K/V) -> fp16 attn
    gather_kernel<<<(M * 32 + 255) / 256, 256>>>(M);

    // O projection: attn @ WO^T + bO + h -> x1 (+ BN1 stats)
    tgemm_k<EPI_BIAS_RESID, true, false, 128><<<dim3(gx, 1), blk, DSMEM_BYTES>>>(
        (const __half*)attnp, wp + OFF_WO, bO, h, nullptr, nullptr,
        stp, stp + D, x1p, nullptr, M, D);

    bn_finalize<<<1, D>>>(stp, stp + D, bn1g, bn1b, bn1p, bn1p + D, M);
    bn_convert<<<cvb, 256>>>(x1p, bn1p, npair);

    // FFN1: relu(BN1(x1) @ W1^T + b1) -> mid fp16 [N, 256]
    tgemm_k<EPI_BIAS_RELU_H, false, false, 128><<<dim3(gx, 2), blk, DSMEM_BYTES>>>(
        (const __half*)bx1p, wp + OFF_W1, b1, nullptr, nullptr, nullptr,
        nullptr, nullptr, nullptr, midp, M, 2 * D);

    // FFN2: mid @ W2^T + b2 + BN1(x1) -> x2 (+ BN2 stats)
    tgemm_k<EPI_BIAS_RESID, true, true, 256><<<dim3(gx, 1), blk, DSMEM_BYTES>>>(
        (const __half*)midp, wp + OFF_W2, b2, x1p, bn1p, bn1p + D,
        stp + 2 * D, stp + 3 * D, x2p, nullptr, M, D);

    bn_finalize<<<1, D>>>(stp + 2 * D, stp + 3 * D, bn2g, bn2b, bn2p, bn2p + D, M);
    bn_apply<<<2048, 256>>>(x2p, bn2p, out, M);
}

// round 11
// speedup vs baseline: 1.4265x; 1.0301x over previous
#include <cuda_runtime.h>
#include <cuda_fp16.h>
#include <math.h>
#include <stdint.h>

#define N_NODES 50000
#define N_EDGES 640000
#define D 128
#define H 8

// ---------------- scratch (static device globals; no allocation) ----------------
__device__ float g_x1[N_NODES * D];
__device__ float g_x2[N_NODES * D];
__device__ float g_stats[4 * D];
__device__ float g_bn1[2 * D];
// fp16x2-packed buffers
__device__ uint32_t g_Qh [N_NODES * D / 2];
__device__ uint32_t g_Kh [N_NODES * D / 2];
__device__ uint32_t g_Vh [N_NODES * D / 2];
__device__ uint32_t g_attn[N_NODES * D / 2];
__device__ uint32_t g_hh [N_NODES * D / 2];
__device__ uint32_t g_bx1[N_NODES * D / 2];
__device__ uint32_t g_midh[N_NODES * D];       // [N, 256] halves = N*128 uint32
// CSR
__device__ int g_rowptr[N_NODES + 1];
__device__ int g_cursor[N_NODES];
__device__ int g_csrc[N_EDGES];
__device__ int g_part[256];
// pre-converted weights (fp16)
#define W_TOTAL 131072
__device__ __half g_w[W_TOTAL];
#define OFF_WQ 0
#define OFF_WK 16384
#define OFF_WV 32768
#define OFF_WO 49152
#define OFF_W1 65536
#define OFF_W2 98304

// ---------------- helpers ----------------
__device__ __forceinline__ uint32_t smem_u32(const void* p) {
    uint32_t a;
    asm("{ .reg .u64 t; cvta.to.shared.u64 t, %1; cvt.u32.u64 %0, t; }" : "=r"(a) : "l"(p));
    return a;
}
__device__ __forceinline__ void ldm_x4(uint32_t& a0, uint32_t& a1, uint32_t& a2, uint32_t& a3,
                                       uint32_t addr) {
    asm volatile("ldmatrix.sync.aligned.m8n8.x4.shared.b16 {%0,%1,%2,%3}, [%4];"
                 : "=r"(a0), "=r"(a1), "=r"(a2), "=r"(a3) : "r"(addr));
}
__device__ __forceinline__ void ldm_x2(uint32_t& b0, uint32_t& b1, uint32_t addr) {
    asm volatile("ldmatrix.sync.aligned.m8n8.x2.shared.b16 {%0,%1}, [%2];"
                 : "=r"(b0), "=r"(b1) : "r"(addr));
}
__device__ __forceinline__ void mma_f16(float* c, uint32_t a0, uint32_t a1, uint32_t a2,
                                        uint32_t a3, uint32_t b0, uint32_t b1) {
    asm volatile(
        "mma.sync.aligned.m16n8k16.row.col.f32.f16.f16.f32 "
        "{%0,%1,%2,%3}, {%4,%5,%6,%7}, {%8,%9}, {%0,%1,%2,%3};"
        : "+f"(c[0]), "+f"(c[1]), "+f"(c[2]), "+f"(c[3])
        : "r"(a0), "r"(a1), "r"(a2), "r"(a3), "r"(b0), "r"(b1));
}
__device__ __forceinline__ uint32_t pack_h2(float a, float b) {
    uint32_t r;
    asm("cvt.rn.f16x2.f32 %0, %1, %2;" : "=r"(r) : "f"(b), "f"(a));
    return r;
}
__device__ __forceinline__ void cp16(uint32_t dst, const void* src) {
    asm volatile("cp.async.cg.shared.global [%0], [%1], 16;" :: "r"(dst), "l"(src));
}
__device__ __forceinline__ void cp16z(uint32_t dst, const void* src, bool pred) {
    int sz = pred ? 16 : 0;
    asm volatile("cp.async.cg.shared.global [%0], [%1], 16, %2;"
                 :: "r"(dst), "l"(src), "r"(sz));
}
#define CP_COMMIT() asm volatile("cp.async.commit_group;" ::: "memory")
#define CP_WAIT0()  asm volatile("cp.async.wait_group 0;" ::: "memory")
#define CP_WAIT1()  asm volatile("cp.async.wait_group 1;" ::: "memory")

// ---------------- fused prep: zero cursor/stats + convert weights + convert h ----
__global__ void prep_kernel(const float* __restrict__ h,
                            const float* __restrict__ WQ, const float* __restrict__ WK,
                            const float* __restrict__ WV, const float* __restrict__ WO,
                            const float* __restrict__ W1, const float* __restrict__ W2,
                            int npair)
{
    int gid = blockIdx.x * blockDim.x + threadIdx.x;
    if (gid < npair) {
        float2 v = ((const float2*)h)[gid];
        g_hh[gid] = pack_h2(v.x, v.y);
    }
    if (gid < W_TOTAL / 2) {
        int elem = gid * 2;
        const float* src;
        int local;
        if (elem < OFF_W1) {
            int m = elem >> 14;
            local = elem & 16383;
            src = (m == 0) ? WQ : (m == 1) ? WK : (m == 2) ? WV : WO;
        } else if (elem < OFF_W2) {
            local = elem - OFF_W1;
            src = W1;
        } else {
            local = elem - OFF_W2;
            src = W2;
        }
        ((uint32_t*)g_w)[gid] = pack_h2(src[local], src[local + 1]);
    }
    if (gid < N_NODES) g_cursor[gid] = 0;
    if (gid < 4 * D) g_stats[gid] = 0.f;
}

// ---------------- CSR build ----------------
__global__ void hist_kernel(const int* __restrict__ dst, int E) {
    int q = blockIdx.x * blockDim.x + threadIdx.x;   // quad index
    int e = q * 4;
    if (e + 4 <= E) {
        int4 d4 = *(const int4*)(dst + e);
        atomicAdd(&g_cursor[d4.x], 1);
        atomicAdd(&g_cursor[d4.y], 1);
        atomicAdd(&g_cursor[d4.z], 1);
        atomicAdd(&g_cursor[d4.w], 1);
    } else {
        for (int i = e; i < E; ++i) atomicAdd(&g_cursor[dst[i]], 1);
    }
}

__global__ __launch_bounds__(256) void scan_local(int n) {
    int tid = threadIdx.x;
    int lane = tid & 31;
    int wid = tid >> 5;
    int i = blockIdx.x * 256 + tid;
    int c = (i < n) ? g_cursor[i] : 0;
    int v = c;
#pragma unroll
    for (int o = 1; o < 32; o <<= 1) {
        int t = __shfl_up_sync(0xffffffffu, v, o);
        if (lane >= o) v += t;
    }
    __shared__ int wsum[8];
    if (lane == 31) wsum[wid] = v;
    __syncthreads();
    if (wid == 0 && lane < 8) {
        int w = wsum[lane];
#pragma unroll
        for (int o = 1; o < 8; o <<= 1) {
            int t = __shfl_up_sync(0xffu, w, o);
            if (lane >= o) w += t;
        }
        wsum[lane] = w;
    }
    __syncthreads();
    int off = (wid > 0) ? wsum[wid - 1] : 0;
    if (i < n) g_rowptr[i] = v - c + off;
    if (tid == 255) g_part[blockIdx.x] = v + off;
}

// scan_final: each block reduces g_part[j < bid] itself (nb <= 256); no scan_part pass
__global__ __launch_bounds__(256) void scan_final(int n, int E) {
    int tid = threadIdx.x;
    int lane = tid & 31;
    int wid = tid >> 5;
    int nb = gridDim.x;
    int p = (tid < nb && tid < (int)blockIdx.x) ? g_part[tid] : 0;
#pragma unroll
    for (int o = 16; o > 0; o >>= 1) p += __shfl_xor_sync(0xffffffffu, p, o);
    __shared__ int wsum[8];
    __shared__ int s_off;
    if (lane == 0) wsum[wid] = p;
    __syncthreads();
    if (tid == 0) {
        int s = 0;
#pragma unroll
        for (int w = 0; w < 8; ++w) s += wsum[w];
        s_off = s;
    }
    __syncthreads();
    int i = blockIdx.x * 256 + tid;
    if (i < n) {
        int r = g_rowptr[i] + s_off;
        g_rowptr[i] = r;
        g_cursor[i] = r;
    }
    if (i == 0) g_rowptr[n] = E;
}

__global__ void scatter_kernel(const int* __restrict__ src, const int* __restrict__ dst, int E) {
    int q = blockIdx.x * blockDim.x + threadIdx.x;
    int e = q * 4;
    if (e + 4 <= E) {
        int4 s4 = *(const int4*)(src + e);
        int4 d4 = *(const int4*)(dst + e);
        g_csrc[atomicAdd(&g_cursor[d4.x], 1)] = s4.x;
        g_csrc[atomicAdd(&g_cursor[d4.y], 1)] = s4.y;
        g_csrc[atomicAdd(&g_cursor[d4.z], 1)] = s4.z;
        g_csrc[atomicAdd(&g_cursor[d4.w], 1)] = s4.w;
    } else {
        for (int i = e; i < E; ++i)
            g_csrc[atomicAdd(&g_cursor[dst[i]], 1)] = src[i];
    }
}

// ---------------- gather attention: fp16 K/V, warp per node ----------------
__device__ __forceinline__ float4 unp4(uint2 u) {
    float2 a = __half22float2(*reinterpret_cast<const __half2*>(&u.x));
    float2 b = __half22float2(*reinterpret_cast<const __half2*>(&u.y));
    return make_float4(a.x, a.y, b.x, b.y);
}

__global__ __launch_bounds__(256) void gather_kernel(int n) {
    int warp = (blockIdx.x * blockDim.x + threadIdx.x) >> 5;
    if (warp >= n) return;
    const int lid = threadIdx.x & 31;
    const int d = warp;
    const size_t base = (size_t)d * (D / 2) + lid * 2;

    float4 q = unp4(*(const uint2*)(g_Qh + base));
    float4 acc = make_float4(0.f, 0.f, 0.f, 0.f);
    float zacc = 0.f;

    int beg = g_rowptr[d], end = g_rowptr[d + 1];
    int i = beg;
    for (; i + 2 <= end; i += 2) {
        int s0 = g_csrc[i], s1 = g_csrc[i + 1];
        size_t o0 = (size_t)s0 * (D / 2) + lid * 2;
        size_t o1 = (size_t)s1 * (D / 2) + lid * 2;
        float4 k0 = unp4(*(const uint2*)(g_Kh + o0));
        float4 k1 = unp4(*(const uint2*)(g_Kh + o1));
        float4 v0 = unp4(*(const uint2*)(g_Vh + o0));
        float4 v1 = unp4(*(const uint2*)(g_Vh + o1));
        float p0 = q.x * k0.x + q.y * k0.y + q.z * k0.z + q.w * k0.w;
        float p1 = q.x * k1.x + q.y * k1.y + q.z * k1.z + q.w * k1.w;
        p0 += __shfl_xor_sync(0xffffffffu, p0, 1);
        p1 += __shfl_xor_sync(0xffffffffu, p1, 1);
        p0 += __shfl_xor_sync(0xffffffffu, p0, 2);
        p1 += __shfl_xor_sync(0xffffffffu, p1, 2);
        float sc0 = __expf(fminf(fmaxf(p0 * 0.25f, -5.f), 5.f));
        float sc1 = __expf(fminf(fmaxf(p1 * 0.25f, -5.f), 5.f));
        acc.x += v0.x * sc0 + v1.x * sc1;
        acc.y += v0.y * sc0 + v1.y * sc1;
        acc.z += v0.z * sc0 + v1.z * sc1;
        acc.w += v0.w * sc0 + v1.w * sc1;
        zacc += sc0 + sc1;
    }
    if (i < end) {
        int s0 = g_csrc[i];
        size_t o0 = (size_t)s0 * (D / 2) + lid * 2;
        float4 k0 = unp4(*(const uint2*)(g_Kh + o0));
        float4 v0 = unp4(*(const uint2*)(g_Vh + o0));
        float p0 = q.x * k0.x + q.y * k0.y + q.z * k0.z + q.w * k0.w;
        p0 += __shfl_xor_sync(0xffffffffu, p0, 1);
        p0 += __shfl_xor_sync(0xffffffffu, p0, 2);
        float sc0 = __expf(fminf(fmaxf(p0 * 0.25f, -5.f), 5.f));
        acc.x += v0.x * sc0; acc.y += v0.y * sc0;
        acc.z += v0.z * sc0; acc.w += v0.w * sc0;
        zacc += sc0;
    }
    float inv = 1.0f / zacc;
    *(uint2*)(g_attn + base) = make_uint2(pack_h2(acc.x * inv, acc.y * inv),
                                          pack_h2(acc.z * inv, acc.w * inv));
}

// ---------------- tensor-core GEMM: single-pass fp16, 2-stage pipeline ----------
enum { EPI_STORE_H = 0, EPI_BIAS_RESID = 1, EPI_BIAS_RELU_H = 2 };

#define BK 64
#define SK 72
#define TILEB (128 * SK * 2)
#define STAGE_B (2 * TILEB)
#define DSMEM_BYTES (2 * STAGE_B)

template <int EPI, bool STATS, bool RESBN, int KT>
__device__ __forceinline__ void tgemm_core(
    const __half* __restrict__ A, const __half* __restrict__ W,
    const float* __restrict__ bias, const float* __restrict__ resid,
    const float* __restrict__ t0, const float* __restrict__ t1,
    float* __restrict__ ssum, float* __restrict__ ssq,
    float* __restrict__ Cf, uint32_t* __restrict__ Ch,
    int M, int ldc, int rowBase, int colBase)
{
    extern __shared__ __align__(16) char sm[];
    const uint32_t smbase = smem_u32(sm);

    const int tid = threadIdx.x;
    const int wid = tid >> 5;
    const int lid = tid & 31;
    const int warp_m = wid & 1;
    const int warp_n = wid >> 1;

    const int ar = (lid & 7) + ((lid >> 3) & 1) * 8;
    const int ac = (lid >> 4) * 8;
    const int br = lid & 7;
    const int bc = ((lid >> 3) & 1) * 8;

    const uint32_t aOff = (uint32_t)((warp_m * 64 + ar) * SK + ac) * 2;
    const uint32_t bOff = (uint32_t)((warp_n * 32 + br) * SK + bc) * 2;

    float acc[4][4][4];
#pragma unroll
    for (int i = 0; i < 4; ++i)
#pragma unroll
        for (int j = 0; j < 4; ++j)
#pragma unroll
            for (int t = 0; t < 4; ++t) acc[i][j][t] = 0.f;

    const int row = tid >> 1;
    const int kh = (tid & 1) * 32;
    const int grow = rowBase + row;
    const bool valid = grow < M;

    const __half* pA = A + (size_t)grow * KT + kh;
    const __half* pW = W + (size_t)(colBase + row) * KT + kh;
    const uint32_t sdst = (uint32_t)(row * SK + kh) * 2;

    auto load_slab = [&](int slab, int stage) {
        uint32_t sb = smbase + stage * STAGE_B + sdst;
        const __half* a = pA + slab * BK;
        const __half* w = pW + slab * BK;
#pragma unroll
        for (int c = 0; c < 4; ++c) cp16z(sb + c * 16, a + c * 8, valid);
#pragma unroll
        for (int c = 0; c < 4; ++c) cp16(sb + TILEB + c * 16, w + c * 8);
        CP_COMMIT();
    };

    constexpr int NSLAB = KT / BK;
    load_slab(0, 0);
#pragma unroll
    for (int s = 0; s < NSLAB; ++s) {
        if (s + 1 < NSLAB) {
            load_slab(s + 1, (s + 1) & 1);
            CP_WAIT1();
        } else {
            CP_WAIT0();
        }
        __syncthreads();

        const uint32_t stA = smbase + (s & 1) * STAGE_B;
        const uint32_t stW = stA + TILEB;
#pragma unroll
        for (int ks = 0; ks < 4; ++ks) {
            const uint32_t k0 = (uint32_t)(ks * 16) * 2;
            uint32_t bh[4][2];
#pragma unroll
            for (int j = 0; j < 4; ++j)
                ldm_x2(bh[j][0], bh[j][1], stW + bOff + (uint32_t)(j * 8 * SK) * 2 + k0);
#pragma unroll
            for (int i = 0; i < 4; ++i) {
                uint32_t a0, a1, a2, a3;
                ldm_x4(a0, a1, a2, a3, stA + aOff + (uint32_t)(i * 16 * SK) * 2 + k0);
#pragma unroll
                for (int j = 0; j < 4; ++j)
                    mma_f16(acc[i][j], a0, a1, a2, a3, bh[j][0], bh[j][1]);
            }
        }
        if (s + 1 < NSLAB) __syncthreads();
    }

    // ---- epilogue ----
    const int rr = lid >> 2;
    const int cc = (lid & 3) * 2;
    float cs[8], cq[8];
    if (STATS) {
#pragma unroll
        for (int t = 0; t < 8; ++t) { cs[t] = 0.f; cq[t] = 0.f; }
    }
#pragma unroll
    for (int i = 0; i < 4; ++i) {
#pragma unroll
        for (int hf = 0; hf < 2; ++hf) {
            int r = rowBase + warp_m * 64 + i * 16 + rr + hf * 8;
            if (r >= M) continue;
#pragma unroll
            for (int j = 0; j < 4; ++j) {
                int col = colBase + warp_n * 32 + j * 8 + cc;
                float v0 = acc[i][j][hf * 2];
                float v1 = acc[i][j][hf * 2 + 1];
                if (EPI == EPI_BIAS_RESID) {
                    v0 += bias[col];
                    v1 += bias[col + 1];
                    float r0 = resid[(size_t)r * D + col];
                    float r1 = resid[(size_t)r * D + col + 1];
                    if (RESBN) {
                        r0 = r0 * t0[col] + t1[col];
                        r1 = r1 * t0[col + 1] + t1[col + 1];
                    }
                    v0 += r0; v1 += r1;
                } else if (EPI == EPI_BIAS_RELU_H) {
                    v0 = fmaxf(v0 + bias[col], 0.f);
                    v1 = fmaxf(v1 + bias[col + 1], 0.f);
                }
                if (STATS) {
                    cs[j * 2] += v0;     cq[j * 2] += v0 * v0;
                    cs[j * 2 + 1] += v1; cq[j * 2 + 1] += v1 * v1;
                }
                if (EPI == EPI_BIAS_RESID) {
                    *(float2*)(Cf + (size_t)r * ldc + col) = make_float2(v0, v1);
                } else {
                    Ch[((size_t)r * ldc + col) >> 1] = pack_h2(v0, v1);
                }
            }
        }
    }
    if (STATS) {
#pragma unroll
        for (int t = 0; t < 8; ++t) {
#pragma unroll
            for (int o = 4; o < 32; o <<= 1) {
                cs[t] += __shfl_xor_sync(0xffffffffu, cs[t], o);
                cq[t] += __shfl_xor_sync(0xffffffffu, cq[t], o);
            }
        }
        if (lid < 4) {
#pragma unroll
            for (int t = 0; t < 8; ++t) {
                int col = colBase + warp_n * 32 + (t >> 1) * 8 + lid * 2 + (t & 1);
                atomicAdd(&ssum[col & (D - 1)], cs[t]);
                atomicAdd(&ssq[col & (D - 1)], cq[t]);
            }
        }
    }
}

template <int EPI, bool STATS, bool RESBN, int KT>
__global__ __launch_bounds__(256, 2) void tgemm_k(
    const __half* __restrict__ A, const __half* __restrict__ W,
    const float* __restrict__ bias, const float* __restrict__ resid,
    const float* __restrict__ t0, const float* __restrict__ t1,
    float* __restrict__ ssum, float* __restrict__ ssq,
    float* __restrict__ Cf, uint32_t* __restrict__ Ch, int M, int ldc)
{
    tgemm_core<EPI, STATS, RESBN, KT>(A, W, bias, resid, t0, t1, ssum, ssq, Cf, Ch,
                                      M, ldc, blockIdx.x * 128, blockIdx.y * 128);
}

__global__ __launch_bounds__(256, 2) void qkv_kernel(int M) {
    int off = (blockIdx.y == 0) ? OFF_WQ : (blockIdx.y == 1) ? OFF_WK : OFF_WV;
    uint32_t* C = (blockIdx.y == 0) ? g_Qh : (blockIdx.y == 1) ? g_Kh : g_Vh;
    tgemm_core<EPI_STORE_H, false, false, 128>(
        (const __half*)g_hh, g_w + off, nullptr, nullptr, nullptr, nullptr,
        nullptr, nullptr, nullptr, C, M, D, blockIdx.x * 128, 0);
}

// ---------------- batch-norm ----------------
__global__ void bn_finalize(const float* __restrict__ sum, const float* __restrict__ sq,
                            const float* __restrict__ g, const float* __restrict__ b,
                            float* __restrict__ scale, float* __restrict__ shift, int M)
{
    int c = threadIdx.x;
    float invM = 1.0f / (float)M;
    float mu = sum[c] * invM;
    float var = sq[c] * invM - mu * mu;
    float sc = g[c] * rsqrtf(var + 1e-5f);
    scale[c] = sc;
    shift[c] = b[c] - mu * sc;
}

__global__ void bn_convert(const float* __restrict__ x1, const float* __restrict__ bn,
                           int npair) {
    int p = blockIdx.x * blockDim.x + threadIdx.x;
    if (p >= npair) return;
    float2 v = ((const float2*)x1)[p];
    int col = (p * 2) & (D - 1);
    g_bx1[p] = pack_h2(v.x * bn[col] + bn[D + col], v.y * bn[col + 1] + bn[D + col + 1]);
}

// bn_apply with inline BN2 finalize (per-block smem precompute) + float4 I/O
__global__ __launch_bounds__(256) void bn_apply(
    const float* __restrict__ x, const float* __restrict__ sum, const float* __restrict__ sq,
    const float* __restrict__ g, const float* __restrict__ b,
    float* __restrict__ out, int M)
{
    __shared__ float s_sc[D], s_sh[D];
    int tid = threadIdx.x;
    if (tid < D) {
        float invM = 1.0f / (float)M;
        float mu = sum[tid] * invM;
        float var = sq[tid] * invM - mu * mu;
        float sc = g[tid] * rsqrtf(var + 1e-5f);
        s_sc[tid] = sc;
        s_sh[tid] = b[tid] - mu * sc;
    }
    __syncthreads();
    int total4 = M * D / 4;
    int stride = gridDim.x * blockDim.x;
    for (int i = blockIdx.x * blockDim.x + tid; i < total4; i += stride) {
        float4 v = ((const float4*)x)[i];
        int col = (i * 4) & (D - 1);
        v.x = v.x * s_sc[col] + s_sh[col];
        v.y = v.y * s_sc[col + 1] + s_sh[col + 1];
        v.z = v.z * s_sc[col + 2] + s_sh[col + 2];
        v.w = v.w * s_sc[col + 3] + s_sh[col + 3];
        ((float4*)out)[i] = v;
    }
}

// ---------------- host launch ----------------
extern "C" void kernel_launch(void* const* d_in, const int* in_sizes, int n_in,
                              void* d_out, int out_size)
{
    const float* h    = (const float*)d_in[0];
    const int*   src  = (const int*)d_in[1];
    const int*   dst  = (const int*)d_in[2];
    const float* WQ   = (const float*)d_in[3];
    const float* WK   = (const float*)d_in[4];
    const float* WV   = (const float*)d_in[5];
    const float* WO   = (const float*)d_in[6];
    const float* bO   = (const float*)d_in[7];
    const float* W1   = (const float*)d_in[8];
    const float* b1   = (const float*)d_in[9];
    const float* W2   = (const float*)d_in[10];
    const float* b2   = (const float*)d_in[11];
    const float* bn1g = (const float*)d_in[12];
    const float* bn1b = (const float*)d_in[13];
    const float* bn2g = (const float*)d_in[14];
    const float* bn2b = (const float*)d_in[15];
    float* out = (float*)d_out;

    int M = in_sizes[0] / D;
    int E = in_sizes[1];
    if (M > N_NODES) M = N_NODES;
    if (E > N_EDGES) E = N_EDGES;

    float *x1p, *x2p, *stp, *bn1p;
    uint32_t *attnp, *bx1p, *midp;
    __half *wp;
    cudaGetSymbolAddress((void**)&x1p, g_x1);
    cudaGetSymbolAddress((void**)&x2p, g_x2);
    cudaGetSymbolAddress((void**)&stp, g_stats);
    cudaGetSymbolAddress((void**)&bn1p, g_bn1);
    cudaGetSymbolAddress((void**)&attnp, g_attn);
    cudaGetSymbolAddress((void**)&bx1p, g_bx1);
    cudaGetSymbolAddress((void**)&midp, g_midh);
    cudaGetSymbolAddress((void**)&wp, g_w);

    cudaFuncSetAttribute(qkv_kernel, cudaFuncAttributeMaxDynamicSharedMemorySize, DSMEM_BYTES);
    cudaFuncSetAttribute(tgemm_k<EPI_BIAS_RESID, true, false, 128>,
                         cudaFuncAttributeMaxDynamicSharedMemorySize, DSMEM_BYTES);
    cudaFuncSetAttribute(tgemm_k<EPI_BIAS_RELU_H, false, false, 128>,
                         cudaFuncAttributeMaxDynamicSharedMemorySize, DSMEM_BYTES);
    cudaFuncSetAttribute(tgemm_k<EPI_BIAS_RESID, true, true, 256>,
                         cudaFuncAttributeMaxDynamicSharedMemorySize, DSMEM_BYTES);

    dim3 blk(256);
    int gx = (M + 127) / 128;
    int nb = (M + 255) / 256;
    int npair = M * D / 2;
    int cvb = (npair + 255) / 256;
    int e4 = (E + 3) / 4;

    // fused prep (zero + weight convert + h convert)
    prep_kernel<<<cvb, 256>>>(h, WQ, WK, WV, WO, W1, W2, npair);

    // CSR build (4 launches: hist, scan_local, scan_final, scatter)
    hist_kernel<<<(e4 + 255) / 256, 256>>>(dst, E);
    scan_local<<<nb, 256>>>(M);
    scan_final<<<nb, 256>>>(M, E);
    scatter_kernel<<<(e4 + 255) / 256, 256>>>(src, dst, E);

    // QKV projections (fp16 single-pass)
    qkv_kernel<<<dim3(gx, 3), blk, DSMEM_BYTES>>>(M);

    // gather attention (fp16 K/V) -> fp16 attn
    gather_kernel<<<(M * 32 + 255) / 256, 256>>>(M);

    // O projection: attn @ WO^T + bO + h -> x1 (+ BN1 stats)
    tgemm_k<EPI_BIAS_RESID, true, false, 128><<<dim3(gx, 1), blk, DSMEM_BYTES>>>(
        (const __half*)attnp, wp + OFF_WO, bO, h, nullptr, nullptr,
        stp, stp + D, x1p, nullptr, M, D);

    bn_finalize<<<1, D>>>(stp, stp + D, bn1g, bn1b, bn1p, bn1p + D, M);
    bn_convert<<<cvb, 256>>>(x1p, bn1p, npair);

    // FFN1: relu(BN1(x1) @ W1^T + b1) -> mid fp16 [N, 256]
    tgemm_k<EPI_BIAS_RELU_H, false, false, 128><<<dim3(gx, 2), blk, DSMEM_BYTES>>>(
        (const __half*)bx1p, wp + OFF_W1, b1, nullptr, nullptr, nullptr,
        nullptr, nullptr, nullptr, midp, M, 2 * D);

    // FFN2: mid @ W2^T + b2 + BN1(x1) -> x2 (+ BN2 stats)
    tgemm_k<EPI_BIAS_RESID, true, true, 256><<<dim3(gx, 1), blk, DSMEM_BYTES>>>(
        (const __half*)midp, wp + OFF_W2, b2, x1p, bn1p, bn1p + D,
        stp + 2 * D, stp + 3 * D, x2p, nullptr, M, D);

    // BN2 apply (finalize fused in-kernel)
    bn_apply<<<1024, 256>>>(x2p, stp + 2 * D, stp + 3 * D, bn2g, bn2b, out, M);
}